// round 7
// baseline (speedup 1.0000x reference)
#include <cuda_runtime.h>
#include <math.h>
#include <stdint.h>

#define BB 2
#define SS 2048
#define HH 1024
#define NHH 16
#define HDD 64
#define MM (BB*SS)          // 4096
#define Y_SIZE (BB*SS*HH)   // 4194304
#define NROWS (BB*NHH*SS)   // 65536

// ---- scratch (no allocation allowed; device globals) ----
__device__ float g_Q[MM*HH];
__device__ float g_K[MM*HH];
__device__ float g_V[MM*HH];
__device__ float g_AO[MM*HH];
__device__ float g_X[MM*HH];
__device__ float g_SUM[16 * NROWS];     // per-ntile partial row sums
__device__ float g_INV[NROWS];          // 1/rowsum
__device__ unsigned int g_MB[BB*SS*SS/32];  // mask bits

__device__ __forceinline__ uint32_t f2tf32(float v) {
    uint32_t r;
    asm("cvt.rna.tf32.f32 %0, %1;" : "=r"(r) : "f"(v));
    return r;
}

#define MMA_TF32(acc, a0,a1,a2,a3, b0,b1) \
    asm volatile("mma.sync.aligned.m16n8k8.row.col.f32.tf32.tf32.f32 " \
        "{%0,%1,%2,%3}, {%4,%5,%6,%7}, {%8,%9}, {%0,%1,%2,%3};" \
        : "+f"((acc)[0]), "+f"((acc)[1]), "+f"((acc)[2]), "+f"((acc)[3]) \
        : "r"(a0), "r"(a1), "r"(a2), "r"(a3), "r"(b0), "r"(b1))

__device__ __forceinline__ void ldsm_x4(uint32_t* r, uint32_t addr) {
    asm volatile("ldmatrix.sync.aligned.m8n8.x4.shared.b16 {%0,%1,%2,%3}, [%4];"
        : "=r"(r[0]), "=r"(r[1]), "=r"(r[2]), "=r"(r[3]) : "r"(addr));
}
__device__ __forceinline__ void ldsm_x2(uint32_t* r, uint32_t addr) {
    asm volatile("ldmatrix.sync.aligned.m8n8.x2.shared.b16 {%0,%1}, [%2];"
        : "=r"(r[0]), "=r"(r[1]) : "r"(addr));
}
#define LDSM_SELS() \
    const int rsel = (lane & 7) + ((lane >> 3) & 1) * 8; \
    const int cA = (lane >> 4) * 4; \
    const int rB = lane & 7; \
    const int cB = ((lane >> 3) & 1) * 4;

// ============================================================
// mask (B,1,S,S) float -> bit per element
// ============================================================
__global__ void __launch_bounds__(256)
maskbits_kernel(const float* __restrict__ mask, unsigned int* __restrict__ mb) {
    int i = blockIdx.x * 256 + threadIdx.x;
    float m = mask[i];
    unsigned int bal = __ballot_sync(0xffffffffu, m != 0.f);
    if ((threadIdx.x & 31) == 0) mb[i >> 5] = bal;
}

// ============================================================
// tf32 warp-MMA GEMM: C[4096,1024] = A[4096,1024] @ W[1024,1024]^T (+res)
// ============================================================
__global__ void __launch_bounds__(256, 2)
gemm_mma_kernel(const float* __restrict__ A, const float* __restrict__ W,
                float* __restrict__ C, const float* __restrict__ res) {
    __shared__ float As[2][128 * 20];
    __shared__ float Ws[2][128 * 20];
    const int tid = threadIdx.x;
    const int wid = tid >> 5, lane = tid & 31;
    const int wm = wid >> 2, wn = wid & 3;
    const int bm = blockIdx.y * 128, bn = blockIdx.x * 128;
    LDSM_SELS();

    const uint32_t AsU = (uint32_t)__cvta_generic_to_shared(&As[0][0]);
    const uint32_t WsU = (uint32_t)__cvta_generic_to_shared(&Ws[0][0]);
    int rowA[4], rowB[4];
#pragma unroll
    for (int im = 0; im < 4; im++) rowA[im] = (wm * 64 + im * 16 + rsel) * 20 + cA;
#pragma unroll
    for (int jn = 0; jn < 4; jn++) rowB[jn] = (wn * 32 + jn * 8 + rB) * 20 + cB;

    const int p0 = tid, p1 = tid + 256;
    const int r0 = p0 >> 2, q0 = (p0 & 3) * 4;
    const int r1 = p1 >> 2, q1 = (p1 & 3) * 4;
    const float* Arow0 = A + (size_t)(bm + r0) * 1024 + q0;
    const float* Arow1 = A + (size_t)(bm + r1) * 1024 + q1;
    const float* Wrow0 = W + (size_t)(bn + r0) * 1024 + q0;
    const float* Wrow1 = W + (size_t)(bn + r1) * 1024 + q1;
    const int s0 = r0 * 20 + q0, s1 = r1 * 20 + q1;

    float acc[4][4][4];
#pragma unroll
    for (int i = 0; i < 4; i++)
#pragma unroll
        for (int j = 0; j < 4; j++)
#pragma unroll
            for (int q = 0; q < 4; q++) acc[i][j][q] = 0.f;

    {
        float4 va0 = *(const float4*)(Arow0);
        float4 va1 = *(const float4*)(Arow1);
        float4 vw0 = *(const float4*)(Wrow0);
        float4 vw1 = *(const float4*)(Wrow1);
        uint32_t* a0 = (uint32_t*)&As[0][s0];
        a0[0]=f2tf32(va0.x); a0[1]=f2tf32(va0.y); a0[2]=f2tf32(va0.z); a0[3]=f2tf32(va0.w);
        uint32_t* a1 = (uint32_t*)&As[0][s1];
        a1[0]=f2tf32(va1.x); a1[1]=f2tf32(va1.y); a1[2]=f2tf32(va1.z); a1[3]=f2tf32(va1.w);
        uint32_t* w0 = (uint32_t*)&Ws[0][s0];
        w0[0]=f2tf32(vw0.x); w0[1]=f2tf32(vw0.y); w0[2]=f2tf32(vw0.z); w0[3]=f2tf32(vw0.w);
        uint32_t* w1 = (uint32_t*)&Ws[0][s1];
        w1[0]=f2tf32(vw1.x); w1[1]=f2tf32(vw1.y); w1[2]=f2tf32(vw1.z); w1[3]=f2tf32(vw1.w);
    }
    __syncthreads();

    for (int c = 0; c < 64; c++) {
        const int buf = c & 1;
        const uint32_t aBuf = AsU + (uint32_t)buf * (128 * 20 * 4);
        const uint32_t wBuf = WsU + (uint32_t)buf * (128 * 20 * 4);
        float4 ra0, ra1, rw0, rw1;
        if (c < 63) {
            const int k0 = (c + 1) * 16;
            ra0 = *(const float4*)(Arow0 + k0);
            ra1 = *(const float4*)(Arow1 + k0);
            rw0 = *(const float4*)(Wrow0 + k0);
            rw1 = *(const float4*)(Wrow1 + k0);
        }

#pragma unroll
        for (int ks = 0; ks < 2; ks++) {
            const int kk = ks * 8;
            uint32_t af[4][4], bf[4][2];
#pragma unroll
            for (int im = 0; im < 4; im++)
                ldsm_x4(af[im], aBuf + (uint32_t)(rowA[im] + kk) * 4);
#pragma unroll
            for (int jn = 0; jn < 4; jn++)
                ldsm_x2(bf[jn], wBuf + (uint32_t)(rowB[jn] + kk) * 4);
#pragma unroll
            for (int im = 0; im < 4; im++)
#pragma unroll
                for (int jn = 0; jn < 4; jn++)
                    MMA_TF32(acc[im][jn], af[im][0], af[im][1], af[im][2], af[im][3],
                             bf[jn][0], bf[jn][1]);
        }

        if (c < 63) {
            const int nxt = buf ^ 1;
            uint32_t* a0 = (uint32_t*)&As[nxt][s0];
            a0[0]=f2tf32(ra0.x); a0[1]=f2tf32(ra0.y); a0[2]=f2tf32(ra0.z); a0[3]=f2tf32(ra0.w);
            uint32_t* a1 = (uint32_t*)&As[nxt][s1];
            a1[0]=f2tf32(ra1.x); a1[1]=f2tf32(ra1.y); a1[2]=f2tf32(ra1.z); a1[3]=f2tf32(ra1.w);
            uint32_t* w0 = (uint32_t*)&Ws[nxt][s0];
            w0[0]=f2tf32(rw0.x); w0[1]=f2tf32(rw0.y); w0[2]=f2tf32(rw0.z); w0[3]=f2tf32(rw0.w);
            uint32_t* w1 = (uint32_t*)&Ws[nxt][s1];
            w1[0]=f2tf32(rw1.x); w1[1]=f2tf32(rw1.y); w1[2]=f2tf32(rw1.z); w1[3]=f2tf32(rw1.w);
        }
        __syncthreads();
    }

    const int g = lane >> 2, t = lane & 3;
#pragma unroll
    for (int im = 0; im < 4; im++) {
        const int rowAo = bm + wm * 64 + im * 16 + g;
        const int rowBo = rowAo + 8;
#pragma unroll
        for (int jn = 0; jn < 4; jn++) {
            const int col = bn + wn * 32 + jn * 8 + 2 * t;
            float2 vA = make_float2(acc[im][jn][0], acc[im][jn][1]);
            float2 vB = make_float2(acc[im][jn][2], acc[im][jn][3]);
            if (res) {
                float2 rA = *(const float2*)(res + (size_t)rowAo * 1024 + col);
                float2 rB2 = *(const float2*)(res + (size_t)rowBo * 1024 + col);
                vA.x += rA.x; vA.y += rA.y; vB.x += rB2.x; vB.y += rB2.y;
            }
            *(float2*)(C + (size_t)rowAo * 1024 + col) = vA;
            *(float2*)(C + (size_t)rowBo * 1024 + col) = vB;
        }
    }
}

// ============================================================
// scores_e: e = mask ? exp((QK^T)/8) : 0 (unnormalized) -> attn buffer,
// plus per-(block-col) partial row sums -> gsum.
// smem: Qs[128x68]@0, Ks[128x68]@8704 (both overlaid by stage[128x132] after
// the MMAs), maskS (512 u32) @17408, sumbuf[512] @17920. 18432 floats total.
// ============================================================
__global__ void __launch_bounds__(256, 2)
scores_e_kernel(const float* __restrict__ Qb, const float* __restrict__ Kb,
                const unsigned int* __restrict__ mb,
                float* __restrict__ attn, float* __restrict__ gsum) {
    extern __shared__ float sm[];
    float* Qs = sm;               // 128 x 68
    float* Ks = sm + 8704;        // 128 x 68
    unsigned int* maskS = (unsigned int*)(sm + 17408);   // 128 x 4 words
    float* sumbuf = sm + 17920;   // 128 x 4
    float* stage = sm;            // 128 x 132 (overlays Qs+Ks)

    const int tid = threadIdx.x;
    const int wid = tid >> 5, lane = tid & 31;
    const int wm = wid >> 2, wn = wid & 3;
    const int bh = blockIdx.z, b = bh >> 4, h = bh & 15;
    const int q0 = blockIdx.y * 128, n0b = blockIdx.x * 128;
    LDSM_SELS();

    const uint32_t QsU = (uint32_t)__cvta_generic_to_shared(Qs);
    const uint32_t KsU = (uint32_t)__cvta_generic_to_shared(Ks);
    int rowA[4], rowBr[4];
#pragma unroll
    for (int im = 0; im < 4; im++) rowA[im] = (wm * 64 + im * 16 + rsel) * 68 + cA;
#pragma unroll
    for (int jn = 0; jn < 4; jn++) rowBr[jn] = (wn * 32 + jn * 8 + rB) * 68 + cB;

    const float* Qbase = Qb + ((size_t)(b * SS + q0)) * HH + h * HDD;
    const float* Kbase = Kb + ((size_t)(b * SS + n0b)) * HH + h * HDD;
#pragma unroll
    for (int j = 0; j < 8; j++) {
        int idx = tid + j * 256;
        int r = idx >> 4, c4 = (idx & 15) * 4;
        float4 vq = *(const float4*)(Qbase + (size_t)r * HH + c4);
        uint32_t* q = (uint32_t*)&Qs[r * 68 + c4];
        q[0]=f2tf32(vq.x); q[1]=f2tf32(vq.y); q[2]=f2tf32(vq.z); q[3]=f2tf32(vq.w);
        float4 vk = *(const float4*)(Kbase + (size_t)r * HH + c4);
        uint32_t* k = (uint32_t*)&Ks[r * 68 + c4];
        k[0]=f2tf32(vk.x); k[1]=f2tf32(vk.y); k[2]=f2tf32(vk.z); k[3]=f2tf32(vk.w);
    }
#pragma unroll
    for (int i = tid; i < 512; i += 256) {     // FIX: was `if (tid < 512)` with 256 threads
        int r = i >> 2, w = i & 3;
        maskS[i] = mb[(size_t)(b * SS + q0 + r) * 64 + (n0b >> 5) + w];
    }
    __syncthreads();

    float acc[4][4][4];
#pragma unroll
    for (int i = 0; i < 4; i++)
#pragma unroll
        for (int j = 0; j < 4; j++)
#pragma unroll
            for (int q = 0; q < 4; q++) acc[i][j][q] = 0.f;

#pragma unroll
    for (int ks = 0; ks < 8; ks++) {
        const int kk = ks * 8;
        uint32_t af[4][4], bf[4][2];
#pragma unroll
        for (int im = 0; im < 4; im++)
            ldsm_x4(af[im], QsU + (uint32_t)(rowA[im] + kk) * 4);
#pragma unroll
        for (int jn = 0; jn < 4; jn++)
            ldsm_x2(bf[jn], KsU + (uint32_t)(rowBr[jn] + kk) * 4);
#pragma unroll
        for (int im = 0; im < 4; im++)
#pragma unroll
            for (int jn = 0; jn < 4; jn++)
                MMA_TF32(acc[im][jn], af[im][0], af[im][1], af[im][2], af[im][3],
                         bf[jn][0], bf[jn][1]);
    }

    // convert to e = mask ? exp(s/8) : 0, accumulate row sums in regs
    const int g = lane >> 2, t = lane & 3;
    float sA[4], sB[4];
#pragma unroll
    for (int im = 0; im < 4; im++) { sA[im] = 0.f; sB[im] = 0.f; }
#pragma unroll
    for (int im = 0; im < 4; im++) {
        const int rAl = wm * 64 + im * 16 + g;
        const int rBl = rAl + 8;
        const unsigned int wA = maskS[rAl * 4 + wn];
        const unsigned int wB = maskS[rBl * 4 + wn];
#pragma unroll
        for (int jn = 0; jn < 4; jn++) {
            const int bp = jn * 8 + 2 * t;
            float e0 = ((wA >> bp) & 1u)       ? __expf(acc[im][jn][0] * 0.125f) : 0.f;
            float e1 = ((wA >> (bp + 1)) & 1u) ? __expf(acc[im][jn][1] * 0.125f) : 0.f;
            float e2 = ((wB >> bp) & 1u)       ? __expf(acc[im][jn][2] * 0.125f) : 0.f;
            float e3 = ((wB >> (bp + 1)) & 1u) ? __expf(acc[im][jn][3] * 0.125f) : 0.f;
            acc[im][jn][0] = e0; acc[im][jn][1] = e1;
            acc[im][jn][2] = e2; acc[im][jn][3] = e3;
            sA[im] += e0 + e1;
            sB[im] += e2 + e3;
        }
    }
    __syncthreads();   // all ldsm complete; safe to overlay Qs/Ks with stage

    // stage e tiles + reduce row sums across the quad (t lanes)
#pragma unroll
    for (int im = 0; im < 4; im++) {
        const int rAl = wm * 64 + im * 16 + g;
        const int rBl = rAl + 8;
#pragma unroll
        for (int jn = 0; jn < 4; jn++) {
            const int col = wn * 32 + jn * 8 + 2 * t;
            *(float2*)&stage[rAl * 132 + col] = make_float2(acc[im][jn][0], acc[im][jn][1]);
            *(float2*)&stage[rBl * 132 + col] = make_float2(acc[im][jn][2], acc[im][jn][3]);
        }
        float a = sA[im], bb2 = sB[im];
        a += __shfl_xor_sync(0xffffffffu, a, 1);
        a += __shfl_xor_sync(0xffffffffu, a, 2);
        bb2 += __shfl_xor_sync(0xffffffffu, bb2, 1);
        bb2 += __shfl_xor_sync(0xffffffffu, bb2, 2);
        if (t == 0) {
            sumbuf[rAl * 4 + wn] = a;
            sumbuf[rBl * 4 + wn] = bb2;
        }
    }
    __syncthreads();

    // coalesced attn write from stage
    float* abase = attn + ((size_t)(bh * SS + q0)) * SS + n0b;
#pragma unroll
    for (int j = 0; j < 16; j++) {
        int idx = tid + j * 256;          // 0..4095 float4s
        int r = idx >> 5, c4 = (idx & 31) * 4;
        float4 v = *(float4*)&stage[r * 132 + c4];
        *(float4*)(abase + (size_t)r * SS + c4) = v;
    }
    if (tid < 128) {
        float s = sumbuf[tid * 4] + sumbuf[tid * 4 + 1] +
                  sumbuf[tid * 4 + 2] + sumbuf[tid * 4 + 3];
        gsum[(size_t)blockIdx.x * NROWS + (size_t)bh * SS + q0 + tid] = s;
    }
}

// ============================================================
// reduce: invs[row] = 1 / sum_nt gsum[nt][row]
// ============================================================
__global__ void __launch_bounds__(256)
rowsum_reduce_kernel(const float* __restrict__ gsum, float* __restrict__ invs) {
    int row = blockIdx.x * 256 + threadIdx.x;
    float s = 0.f;
#pragma unroll
    for (int nt = 0; nt < 16; nt++) s += gsum[(size_t)nt * NROWS + row];
    invs[row] = 1.f / s;
}

// ============================================================
// AV via MMA + in-place attn normalization writeback.
// ============================================================
__global__ void __launch_bounds__(256, 3)
av_mma_kernel(float* __restrict__ attn, const float* __restrict__ Vb,
              const float* __restrict__ invs, float* __restrict__ Ob) {
    extern __shared__ float sm[];
    float* Ps = sm;               // 128 x 68
    float* Vs = sm + 128 * 68;    // 64 x 68  ([d][k])
    const int tid = threadIdx.x;
    const int wid = tid >> 5, lane = tid & 31;
    const int wm = wid >> 1, wn = wid & 1;       // 4 x 2
    const int bh = blockIdx.y, b = bh >> 4, h = bh & 15;
    const int q0 = blockIdx.x * 128;
    LDSM_SELS();

    const uint32_t PsU = (uint32_t)__cvta_generic_to_shared(Ps);
    const uint32_t VsU = (uint32_t)__cvta_generic_to_shared(Vs);
    int rowA[2], rowBr[4];
#pragma unroll
    for (int im = 0; im < 2; im++) rowA[im] = (wm * 32 + im * 16 + rsel) * 68 + cA;
#pragma unroll
    for (int jn = 0; jn < 4; jn++) rowBr[jn] = (wn * 32 + jn * 8 + rB) * 68 + cB;

    float acc[2][4][4];
#pragma unroll
    for (int i = 0; i < 2; i++)
#pragma unroll
        for (int j = 0; j < 4; j++)
#pragma unroll
            for (int q = 0; q < 4; q++) acc[i][j][q] = 0.f;

    float* Pbase = attn + ((size_t)(bh * SS + q0)) * SS;
    const float* Vbase = Vb + ((size_t)(b * SS)) * HH + h * HDD;
    const float* invp = invs + (size_t)bh * SS + q0;

    for (int k0 = 0; k0 < SS; k0 += 64) {
#pragma unroll
        for (int j = 0; j < 8; j++) {
            int idx = tid + j * 256;
            int r = idx >> 4, c4 = (idx & 15) * 4;
            float* gp = Pbase + (size_t)r * SS + k0 + c4;
            float4 v = *(const float4*)gp;
            float iv = invp[r];
            v.x *= iv; v.y *= iv; v.z *= iv; v.w *= iv;
            *(float4*)gp = v;                       // normalized attn writeback
            uint32_t* q = (uint32_t*)&Ps[r * 68 + c4];
            q[0]=f2tf32(v.x); q[1]=f2tf32(v.y); q[2]=f2tf32(v.z); q[3]=f2tf32(v.w);
        }
#pragma unroll
        for (int j = 0; j < 4; j++) {
            int idx = tid + j * 256;
            int r = idx >> 4, c4 = (idx & 15) * 4;
            float4 v = *(const float4*)(Vbase + (size_t)(k0 + r) * HH + c4);
            Vs[(c4 + 0) * 68 + r] = __uint_as_float(f2tf32(v.x));
            Vs[(c4 + 1) * 68 + r] = __uint_as_float(f2tf32(v.y));
            Vs[(c4 + 2) * 68 + r] = __uint_as_float(f2tf32(v.z));
            Vs[(c4 + 3) * 68 + r] = __uint_as_float(f2tf32(v.w));
        }
        __syncthreads();

#pragma unroll
        for (int ks = 0; ks < 8; ks++) {
            const int kk = ks * 8;
            uint32_t af[2][4], bf[4][2];
#pragma unroll
            for (int im = 0; im < 2; im++)
                ldsm_x4(af[im], PsU + (uint32_t)(rowA[im] + kk) * 4);
#pragma unroll
            for (int jn = 0; jn < 4; jn++)
                ldsm_x2(bf[jn], VsU + (uint32_t)(rowBr[jn] + kk) * 4);
#pragma unroll
            for (int im = 0; im < 2; im++)
#pragma unroll
                for (int jn = 0; jn < 4; jn++)
                    MMA_TF32(acc[im][jn], af[im][0], af[im][1], af[im][2], af[im][3],
                             bf[jn][0], bf[jn][1]);
        }
        __syncthreads();
    }

    const int g = lane >> 2, t = lane & 3;
#pragma unroll
    for (int im = 0; im < 2; im++) {
        const int rowAo = q0 + wm * 32 + im * 16 + g;
        const int rowBo = rowAo + 8;
#pragma unroll
        for (int jn = 0; jn < 4; jn++) {
            const int col = h * HDD + wn * 32 + jn * 8 + 2 * t;
            *(float2*)(Ob + (size_t)(b * SS + rowAo) * HH + col) =
                make_float2(acc[im][jn][0], acc[im][jn][1]);
            *(float2*)(Ob + (size_t)(b * SS + rowBo) * HH + col) =
                make_float2(acc[im][jn][2], acc[im][jn][3]);
        }
    }
}

// ============================================================
// LayerNorm
// ============================================================
__global__ void ln_kernel(const float* __restrict__ X,
                          const float* __restrict__ w,
                          const float* __restrict__ bias,
                          float* __restrict__ Y) {
    __shared__ float red[8];
    __shared__ float bc;
    const int row = blockIdx.x;
    const float* x = X + (size_t)row * HH;
    const int tid = threadIdx.x, lane = tid & 31, warp = tid >> 5;

    float s = 0.f;
    for (int c = tid; c < HH; c += 256) s += x[c];
#pragma unroll
    for (int o = 16; o; o >>= 1) s += __shfl_xor_sync(0xffffffffu, s, o);
    if (lane == 0) red[warp] = s;
    __syncthreads();
    if (tid == 0) {
        float tt = 0.f;
        for (int i = 0; i < 8; i++) tt += red[i];
        bc = tt / HH;
    }
    __syncthreads();
    float mu = bc;

    float v = 0.f;
    for (int c = tid; c < HH; c += 256) { float d = x[c] - mu; v += d * d; }
#pragma unroll
    for (int o = 16; o; o >>= 1) v += __shfl_xor_sync(0xffffffffu, v, o);
    if (lane == 0) red[warp] = v;
    __syncthreads();
    if (tid == 0) {
        float tt = 0.f;
        for (int i = 0; i < 8; i++) tt += red[i];
        bc = rsqrtf(tt / HH + 1e-6f);
    }
    __syncthreads();
    float inv = bc;

    for (int c = tid; c < HH; c += 256)
        Y[(size_t)row * HH + c] = (x[c] - mu) * inv * w[c] + bias[c];
}

// ============================================================
extern "C" void kernel_launch(void* const* d_in, const int* in_sizes, int n_in,
                              void* d_out, int out_size) {
    const float* enc  = (const float*)d_in[0];
    const float* mask = (const float*)d_in[1];
    const float* WQ   = (const float*)d_in[2];
    const float* WK   = (const float*)d_in[3];
    const float* WV   = (const float*)d_in[4];
    const float* WO   = (const float*)d_in[5];
    const float* lnw  = (const float*)d_in[6];
    const float* lnb  = (const float*)d_in[7];

    float* y    = (float*)d_out;              // (B,S,H)
    float* attn = y + (size_t)Y_SIZE;         // (B,NH,S,S)

    float *Qp, *Kp, *Vp, *Op, *Xp, *Sp, *Ip;
    unsigned int* Mp;
    cudaGetSymbolAddress((void**)&Qp, g_Q);
    cudaGetSymbolAddress((void**)&Kp, g_K);
    cudaGetSymbolAddress((void**)&Vp, g_V);
    cudaGetSymbolAddress((void**)&Op, g_AO);
    cudaGetSymbolAddress((void**)&Xp, g_X);
    cudaGetSymbolAddress((void**)&Sp, g_SUM);
    cudaGetSymbolAddress((void**)&Ip, g_INV);
    cudaGetSymbolAddress((void**)&Mp, g_MB);

    maskbits_kernel<<<BB*SS*SS/256, 256>>>(mask, Mp);

    dim3 gt(HH / 128, MM / 128);   // (8, 32)
    gemm_mma_kernel<<<gt, 256>>>(enc, WQ, Qp, nullptr);
    gemm_mma_kernel<<<gt, 256>>>(enc, WK, Kp, nullptr);
    gemm_mma_kernel<<<gt, 256>>>(enc, WV, Vp, nullptr);

    const int sc_smem = 18432 * (int)sizeof(float);   // 73728
    cudaFuncSetAttribute(scores_e_kernel,
                         cudaFuncAttributeMaxDynamicSharedMemorySize, sc_smem);
    scores_e_kernel<<<dim3(SS / 128, SS / 128, BB * NHH), 256, sc_smem>>>(Qp, Kp, Mp, attn, Sp);

    rowsum_reduce_kernel<<<NROWS / 256, 256>>>(Sp, Ip);

    const int av_smem = (128 + 64) * 68 * (int)sizeof(float); // 52224
    cudaFuncSetAttribute(av_mma_kernel,
                         cudaFuncAttributeMaxDynamicSharedMemorySize, av_smem);
    av_mma_kernel<<<dim3(SS / 128, BB * NHH), 256, av_smem>>>(attn, Vp, Ip, Op);

    gemm_mma_kernel<<<gt, 256>>>(Op, WO, Xp, enc);

    ln_kernel<<<MM, 256>>>(Xp, lnw, lnb, y);
}

// round 10
// speedup vs baseline: 1.1795x; 1.1795x over previous
#include <cuda_runtime.h>
#include <math.h>
#include <stdint.h>

#define BB 2
#define SS 2048
#define HH 1024
#define NHH 16
#define HDD 64
#define MM (BB*SS)          // 4096
#define Y_SIZE (BB*SS*HH)   // 4194304
#define NROWS (BB*NHH*SS)   // 65536

// ---- scratch (no allocation allowed; device globals) ----
__device__ float g_Q[MM*HH];
__device__ float g_K[MM*HH];
__device__ float g_V[MM*HH];
__device__ float g_AO[MM*HH];
__device__ float g_X[MM*HH];
__device__ float g_INV[NROWS];              // 1/rowsum
__device__ unsigned int g_MB[BB*SS*SS/32];  // mask bits

__device__ __forceinline__ uint32_t f2tf32(float v) {
    uint32_t r;
    asm("cvt.rna.tf32.f32 %0, %1;" : "=r"(r) : "f"(v));
    return r;
}

#define MMA_TF32(acc, a0,a1,a2,a3, b0,b1) \
    asm volatile("mma.sync.aligned.m16n8k8.row.col.f32.tf32.tf32.f32 " \
        "{%0,%1,%2,%3}, {%4,%5,%6,%7}, {%8,%9}, {%0,%1,%2,%3};" \
        : "+f"((acc)[0]), "+f"((acc)[1]), "+f"((acc)[2]), "+f"((acc)[3]) \
        : "r"(a0), "r"(a1), "r"(a2), "r"(a3), "r"(b0), "r"(b1))

__device__ __forceinline__ void ldsm_x4(uint32_t* r, uint32_t addr) {
    asm volatile("ldmatrix.sync.aligned.m8n8.x4.shared.b16 {%0,%1,%2,%3}, [%4];"
        : "=r"(r[0]), "=r"(r[1]), "=r"(r[2]), "=r"(r[3]) : "r"(addr));
}
__device__ __forceinline__ void ldsm_x2(uint32_t* r, uint32_t addr) {
    asm volatile("ldmatrix.sync.aligned.m8n8.x2.shared.b16 {%0,%1}, [%2];"
        : "=r"(r[0]), "=r"(r[1]) : "r"(addr));
}
#define LDSM_SELS() \
    const int rsel = (lane & 7) + ((lane >> 3) & 1) * 8; \
    const int cA = (lane >> 4) * 4; \
    const int rB = lane & 7; \
    const int cB = ((lane >> 3) & 1) * 4;

// ============================================================
// mask (B,1,S,S) float -> bit per element
// ============================================================
__global__ void __launch_bounds__(256)
maskbits_kernel(const float* __restrict__ mask, unsigned int* __restrict__ mb) {
    int i = blockIdx.x * 256 + threadIdx.x;
    float m = mask[i];
    unsigned int bal = __ballot_sync(0xffffffffu, m != 0.f);
    if ((threadIdx.x & 31) == 0) mb[i >> 5] = bal;
}

// ============================================================
// tf32 warp-MMA GEMM: C[4096,1024] = A[4096,1024] @ W[1024,1024]^T (+res)
// IMPORTANT: smem stores go through cvt.rna.tf32 (round-to-nearest).
// Raw-f32 (HW truncation) is BIASED and pushed attn_dist error to 2e-3.
// ============================================================
__global__ void __launch_bounds__(256, 2)
gemm_mma_kernel(const float* __restrict__ A, const float* __restrict__ W,
                float* __restrict__ C, const float* __restrict__ res) {
    __shared__ float As[2][128 * 20];
    __shared__ float Ws[2][128 * 20];
    const int tid = threadIdx.x;
    const int wid = tid >> 5, lane = tid & 31;
    const int wm = wid >> 2, wn = wid & 3;
    const int bm = blockIdx.y * 128, bn = blockIdx.x * 128;
    LDSM_SELS();

    const uint32_t AsU = (uint32_t)__cvta_generic_to_shared(&As[0][0]);
    const uint32_t WsU = (uint32_t)__cvta_generic_to_shared(&Ws[0][0]);
    int rowA[4], rowB[4];
#pragma unroll
    for (int im = 0; im < 4; im++) rowA[im] = (wm * 64 + im * 16 + rsel) * 20 + cA;
#pragma unroll
    for (int jn = 0; jn < 4; jn++) rowB[jn] = (wn * 32 + jn * 8 + rB) * 20 + cB;

    const int p0 = tid, p1 = tid + 256;
    const int r0 = p0 >> 2, q0 = (p0 & 3) * 4;
    const int r1 = p1 >> 2, q1 = (p1 & 3) * 4;
    const float* Arow0 = A + (size_t)(bm + r0) * 1024 + q0;
    const float* Arow1 = A + (size_t)(bm + r1) * 1024 + q1;
    const float* Wrow0 = W + (size_t)(bn + r0) * 1024 + q0;
    const float* Wrow1 = W + (size_t)(bn + r1) * 1024 + q1;
    const int s0 = r0 * 20 + q0, s1 = r1 * 20 + q1;

    float acc[4][4][4];
#pragma unroll
    for (int i = 0; i < 4; i++)
#pragma unroll
        for (int j = 0; j < 4; j++)
#pragma unroll
            for (int q = 0; q < 4; q++) acc[i][j][q] = 0.f;

    {
        float4 va0 = *(const float4*)(Arow0);
        float4 va1 = *(const float4*)(Arow1);
        float4 vw0 = *(const float4*)(Wrow0);
        float4 vw1 = *(const float4*)(Wrow1);
        uint32_t* a0 = (uint32_t*)&As[0][s0];
        a0[0]=f2tf32(va0.x); a0[1]=f2tf32(va0.y); a0[2]=f2tf32(va0.z); a0[3]=f2tf32(va0.w);
        uint32_t* a1 = (uint32_t*)&As[0][s1];
        a1[0]=f2tf32(va1.x); a1[1]=f2tf32(va1.y); a1[2]=f2tf32(va1.z); a1[3]=f2tf32(va1.w);
        uint32_t* w0 = (uint32_t*)&Ws[0][s0];
        w0[0]=f2tf32(vw0.x); w0[1]=f2tf32(vw0.y); w0[2]=f2tf32(vw0.z); w0[3]=f2tf32(vw0.w);
        uint32_t* w1 = (uint32_t*)&Ws[0][s1];
        w1[0]=f2tf32(vw1.x); w1[1]=f2tf32(vw1.y); w1[2]=f2tf32(vw1.z); w1[3]=f2tf32(vw1.w);
    }
    __syncthreads();

    for (int c = 0; c < 64; c++) {
        const int buf = c & 1;
        const uint32_t aBuf = AsU + (uint32_t)buf * (128 * 20 * 4);
        const uint32_t wBuf = WsU + (uint32_t)buf * (128 * 20 * 4);
        float4 ra0, ra1, rw0, rw1;
        if (c < 63) {
            const int k0 = (c + 1) * 16;
            ra0 = *(const float4*)(Arow0 + k0);
            ra1 = *(const float4*)(Arow1 + k0);
            rw0 = *(const float4*)(Wrow0 + k0);
            rw1 = *(const float4*)(Wrow1 + k0);
        }

#pragma unroll
        for (int ks = 0; ks < 2; ks++) {
            const int kk = ks * 8;
            uint32_t af[4][4], bf[4][2];
#pragma unroll
            for (int im = 0; im < 4; im++)
                ldsm_x4(af[im], aBuf + (uint32_t)(rowA[im] + kk) * 4);
#pragma unroll
            for (int jn = 0; jn < 4; jn++)
                ldsm_x2(bf[jn], wBuf + (uint32_t)(rowB[jn] + kk) * 4);
#pragma unroll
            for (int im = 0; im < 4; im++)
#pragma unroll
                for (int jn = 0; jn < 4; jn++)
                    MMA_TF32(acc[im][jn], af[im][0], af[im][1], af[im][2], af[im][3],
                             bf[jn][0], bf[jn][1]);
        }

        if (c < 63) {
            const int nxt = buf ^ 1;
            uint32_t* a0 = (uint32_t*)&As[nxt][s0];
            a0[0]=f2tf32(ra0.x); a0[1]=f2tf32(ra0.y); a0[2]=f2tf32(ra0.z); a0[3]=f2tf32(ra0.w);
            uint32_t* a1 = (uint32_t*)&As[nxt][s1];
            a1[0]=f2tf32(ra1.x); a1[1]=f2tf32(ra1.y); a1[2]=f2tf32(ra1.z); a1[3]=f2tf32(ra1.w);
            uint32_t* w0 = (uint32_t*)&Ws[nxt][s0];
            w0[0]=f2tf32(rw0.x); w0[1]=f2tf32(rw0.y); w0[2]=f2tf32(rw0.z); w0[3]=f2tf32(rw0.w);
            uint32_t* w1 = (uint32_t*)&Ws[nxt][s1];
            w1[0]=f2tf32(rw1.x); w1[1]=f2tf32(rw1.y); w1[2]=f2tf32(rw1.z); w1[3]=f2tf32(rw1.w);
        }
        __syncthreads();
    }

    const int g = lane >> 2, t = lane & 3;
#pragma unroll
    for (int im = 0; im < 4; im++) {
        const int rowAo = bm + wm * 64 + im * 16 + g;
        const int rowBo = rowAo + 8;
#pragma unroll
        for (int jn = 0; jn < 4; jn++) {
            const int col = bn + wn * 32 + jn * 8 + 2 * t;
            float2 vA = make_float2(acc[im][jn][0], acc[im][jn][1]);
            float2 vB = make_float2(acc[im][jn][2], acc[im][jn][3]);
            if (res) {
                float2 rA = *(const float2*)(res + (size_t)rowAo * 1024 + col);
                float2 rB2 = *(const float2*)(res + (size_t)rowBo * 1024 + col);
                vA.x += rA.x; vA.y += rA.y; vB.x += rB2.x; vB.y += rB2.y;
            }
            *(float2*)(C + (size_t)rowAo * 1024 + col) = vA;
            *(float2*)(C + (size_t)rowBo * 1024 + col) = vB;
        }
    }
}

// ============================================================
// Pass A: inv[row] = 1 / sum_k (mask ? exp(q.k/8) : 0). No large writes.
// ============================================================
__global__ void __launch_bounds__(256, 2)
inv_kernel(const float* __restrict__ Qb, const float* __restrict__ Kb,
           const unsigned int* __restrict__ mb, float* __restrict__ invs) {
    extern __shared__ float sm[];
    float* Qs = sm;
    float* Ks = sm + 8704;
    float* sumbuf = sm + 13056;
    unsigned int* maskS = (unsigned int*)(sm + 13568);

    const int tid = threadIdx.x;
    const int wid = tid >> 5, lane = tid & 31;
    const int wm = wid >> 2, wn = wid & 3;
    const int bh = blockIdx.y, b = bh >> 4, h = bh & 15;
    const int q0 = blockIdx.x * 128;
    LDSM_SELS();
    const int g = lane >> 2, t = lane & 3;

    const uint32_t QsU = (uint32_t)__cvta_generic_to_shared(Qs);
    const uint32_t KsU = (uint32_t)__cvta_generic_to_shared(Ks);
    int rowA[4], rowBr[2];
#pragma unroll
    for (int im = 0; im < 4; im++) rowA[im] = (wm * 64 + im * 16 + rsel) * 68 + cA;
#pragma unroll
    for (int jn = 0; jn < 2; jn++) rowBr[jn] = (wn * 16 + jn * 8 + rB) * 68 + cB;

    const float* Qbase = Qb + ((size_t)(b * SS + q0)) * HH + h * HDD;
    const float* Kbase = Kb + ((size_t)b * SS) * HH + h * HDD;
#pragma unroll
    for (int j = 0; j < 8; j++) {
        int idx = tid + j * 256;
        int r = idx >> 4, c4 = (idx & 15) * 4;
        float4 vq = *(const float4*)(Qbase + (size_t)r * HH + c4);
        uint32_t* q = (uint32_t*)&Qs[r * 68 + c4];
        q[0]=f2tf32(vq.x); q[1]=f2tf32(vq.y); q[2]=f2tf32(vq.z); q[3]=f2tf32(vq.w);
    }

    float rsA[4], rsB[4];
#pragma unroll
    for (int im = 0; im < 4; im++) { rsA[im] = 0.f; rsB[im] = 0.f; }

    for (int kt = 0; kt < 32; kt++) {
        const int n0 = kt * 64;
        __syncthreads();
#pragma unroll
        for (int j = 0; j < 4; j++) {
            int idx = tid + j * 256;          // 0..1023
            int r = idx >> 4, c4 = (idx & 15) * 4;
            float4 vk = *(const float4*)(Kbase + (size_t)(n0 + r) * HH + c4);
            uint32_t* k = (uint32_t*)&Ks[r * 68 + c4];
            k[0]=f2tf32(vk.x); k[1]=f2tf32(vk.y); k[2]=f2tf32(vk.z); k[3]=f2tf32(vk.w);
        }
        if (tid < 256) {
            int r = tid >> 1, w = tid & 1;
            maskS[tid] = mb[(size_t)(b * SS + q0 + r) * 64 + (n0 >> 5) + w];
        }
        __syncthreads();

        float acc[4][2][4];
#pragma unroll
        for (int i = 0; i < 4; i++)
#pragma unroll
            for (int j = 0; j < 2; j++)
#pragma unroll
                for (int q = 0; q < 4; q++) acc[i][j][q] = 0.f;

#pragma unroll
        for (int ks = 0; ks < 8; ks++) {
            const int kk = ks * 8;
            uint32_t af[4][4], bf[2][2];
#pragma unroll
            for (int im = 0; im < 4; im++)
                ldsm_x4(af[im], QsU + (uint32_t)(rowA[im] + kk) * 4);
#pragma unroll
            for (int jn = 0; jn < 2; jn++)
                ldsm_x2(bf[jn], KsU + (uint32_t)(rowBr[jn] + kk) * 4);
#pragma unroll
            for (int im = 0; im < 4; im++)
#pragma unroll
                for (int jn = 0; jn < 2; jn++)
                    MMA_TF32(acc[im][jn], af[im][0], af[im][1], af[im][2], af[im][3],
                             bf[jn][0], bf[jn][1]);
        }

#pragma unroll
        for (int im = 0; im < 4; im++) {
            const int rAl = wm * 64 + im * 16 + g;
            const int rBl = rAl + 8;
#pragma unroll
            for (int jn = 0; jn < 2; jn++) {
                const int bp = wn * 16 + jn * 8 + 2 * t;
                const unsigned int wA = maskS[rAl * 2 + (bp >> 5)];
                const unsigned int wB = maskS[rBl * 2 + (bp >> 5)];
                const int bi = bp & 31;
                if ((wA >> bi) & 1u)       rsA[im] += __expf(acc[im][jn][0] * 0.125f);
                if ((wA >> (bi + 1)) & 1u) rsA[im] += __expf(acc[im][jn][1] * 0.125f);
                if ((wB >> bi) & 1u)       rsB[im] += __expf(acc[im][jn][2] * 0.125f);
                if ((wB >> (bi + 1)) & 1u) rsB[im] += __expf(acc[im][jn][3] * 0.125f);
            }
        }
    }

#pragma unroll
    for (int im = 0; im < 4; im++) {
        float a = rsA[im], bb = rsB[im];
        a += __shfl_xor_sync(0xffffffffu, a, 1);
        a += __shfl_xor_sync(0xffffffffu, a, 2);
        bb += __shfl_xor_sync(0xffffffffu, bb, 1);
        bb += __shfl_xor_sync(0xffffffffu, bb, 2);
        if (t == 0) {
            sumbuf[(wm * 64 + im * 16 + g) * 4 + wn] = a;
            sumbuf[(wm * 64 + im * 16 + g + 8) * 4 + wn] = bb;
        }
    }
    __syncthreads();
    if (tid < 128) {
        float s = sumbuf[tid * 4] + sumbuf[tid * 4 + 1] +
                  sumbuf[tid * 4 + 2] + sumbuf[tid * 4 + 3];
        invs[(size_t)bh * SS + q0 + tid] = (s > 0.f) ? 1.f / s : 0.f;
    }
}

// ============================================================
// Pass B: fused attn + AV. Stage holds FULL FP32 attn (exact store values);
// AV MMA consumes the same bits (HW truncates f32->tf32; only affects y).
// ============================================================
__global__ void __launch_bounds__(256, 2)
fused_attn_kernel(const float* __restrict__ Qb, const float* __restrict__ Kb,
                  const float* __restrict__ Vb, const unsigned int* __restrict__ mb,
                  const float* __restrict__ invs,
                  float* __restrict__ attn, float* __restrict__ Ob) {
    extern __shared__ float sm[];
    float* Qs = sm;
    float* Ks = sm + 8704;
    float* Vs = sm + 13056;
    float* stage = sm + 17408;
    unsigned int* maskS = (unsigned int*)(sm + 26112);
    float* invS = sm + 26368;

    const int tid = threadIdx.x;
    const int wid = tid >> 5, lane = tid & 31;
    const int wm = wid >> 2, wn = wid & 3;     // 2 x 4 for both phases
    const int bh = blockIdx.y, b = bh >> 4, h = bh & 15;
    const int q0 = blockIdx.x * 128;
    LDSM_SELS();
    const int g = lane >> 2, t = lane & 3;

    const uint32_t QsU = (uint32_t)__cvta_generic_to_shared(Qs);
    const uint32_t KsU = (uint32_t)__cvta_generic_to_shared(Ks);
    const uint32_t VsU = (uint32_t)__cvta_generic_to_shared(Vs);
    const uint32_t StU = (uint32_t)__cvta_generic_to_shared(stage);

    int rowQ[4], rowK[2], rowV[2];
#pragma unroll
    for (int im = 0; im < 4; im++) rowQ[im] = (wm * 64 + im * 16 + rsel) * 68 + cA;
#pragma unroll
    for (int jn = 0; jn < 2; jn++) rowK[jn] = (wn * 16 + jn * 8 + rB) * 68 + cB;
#pragma unroll
    for (int jd = 0; jd < 2; jd++) rowV[jd] = (wn * 16 + jd * 8 + rB) * 68 + cB;

    const float* Qbase = Qb + ((size_t)(b * SS + q0)) * HH + h * HDD;
    const float* Kbase = Kb + ((size_t)b * SS) * HH + h * HDD;
    const float* Vbase = Vb + ((size_t)b * SS) * HH + h * HDD;
#pragma unroll
    for (int j = 0; j < 8; j++) {
        int idx = tid + j * 256;
        int r = idx >> 4, c4 = (idx & 15) * 4;
        float4 vq = *(const float4*)(Qbase + (size_t)r * HH + c4);
        uint32_t* q = (uint32_t*)&Qs[r * 68 + c4];
        q[0]=f2tf32(vq.x); q[1]=f2tf32(vq.y); q[2]=f2tf32(vq.z); q[3]=f2tf32(vq.w);
    }
    if (tid < 128) invS[tid] = invs[(size_t)bh * SS + q0 + tid];

    float accO[4][2][4];
#pragma unroll
    for (int i = 0; i < 4; i++)
#pragma unroll
        for (int j = 0; j < 2; j++)
#pragma unroll
            for (int q = 0; q < 4; q++) accO[i][j][q] = 0.f;

    for (int kt = 0; kt < 32; kt++) {
        const int k0 = kt * 64;
        __syncthreads();
#pragma unroll
        for (int j = 0; j < 4; j++) {
            int idx = tid + j * 256;
            int r = idx >> 4, c4 = (idx & 15) * 4;
            float4 vk = *(const float4*)(Kbase + (size_t)(k0 + r) * HH + c4);
            uint32_t* k = (uint32_t*)&Ks[r * 68 + c4];
            k[0]=f2tf32(vk.x); k[1]=f2tf32(vk.y); k[2]=f2tf32(vk.z); k[3]=f2tf32(vk.w);
            float4 vv = *(const float4*)(Vbase + (size_t)(k0 + r) * HH + c4);
            Vs[(c4 + 0) * 68 + r] = __uint_as_float(f2tf32(vv.x));
            Vs[(c4 + 1) * 68 + r] = __uint_as_float(f2tf32(vv.y));
            Vs[(c4 + 2) * 68 + r] = __uint_as_float(f2tf32(vv.z));
            Vs[(c4 + 3) * 68 + r] = __uint_as_float(f2tf32(vv.w));
        }
        if (tid < 256) {
            int r = tid >> 1, w = tid & 1;
            maskS[tid] = mb[(size_t)(b * SS + q0 + r) * 64 + (k0 >> 5) + w];
        }
        __syncthreads();

        // --- S = Q K^T ---
        float acc[4][2][4];
#pragma unroll
        for (int i = 0; i < 4; i++)
#pragma unroll
            for (int j = 0; j < 2; j++)
#pragma unroll
                for (int q = 0; q < 4; q++) acc[i][j][q] = 0.f;
#pragma unroll
        for (int ks = 0; ks < 8; ks++) {
            const int kk = ks * 8;
            uint32_t af[4][4], bf[2][2];
#pragma unroll
            for (int im = 0; im < 4; im++)
                ldsm_x4(af[im], QsU + (uint32_t)(rowQ[im] + kk) * 4);
#pragma unroll
            for (int jn = 0; jn < 2; jn++)
                ldsm_x2(bf[jn], KsU + (uint32_t)(rowK[jn] + kk) * 4);
#pragma unroll
            for (int im = 0; im < 4; im++)
#pragma unroll
                for (int jn = 0; jn < 2; jn++)
                    MMA_TF32(acc[im][jn], af[im][0], af[im][1], af[im][2], af[im][3],
                             bf[jn][0], bf[jn][1]);
        }

        // --- attn = mask ? exp(S/8)*inv : 0 -> stage (FULL FP32) ---
#pragma unroll
        for (int im = 0; im < 4; im++) {
            const int rAl = wm * 64 + im * 16 + g;
            const int rBl = rAl + 8;
            const float ivA = invS[rAl], ivB = invS[rBl];
#pragma unroll
            for (int jn = 0; jn < 2; jn++) {
                const int bp = wn * 16 + jn * 8 + 2 * t;
                const unsigned int wA = maskS[rAl * 2 + (bp >> 5)];
                const unsigned int wB = maskS[rBl * 2 + (bp >> 5)];
                const int bi = bp & 31;
                float e0 = ((wA >> bi) & 1u)       ? __expf(acc[im][jn][0] * 0.125f) * ivA : 0.f;
                float e1 = ((wA >> (bi + 1)) & 1u) ? __expf(acc[im][jn][1] * 0.125f) * ivA : 0.f;
                float e2 = ((wB >> bi) & 1u)       ? __expf(acc[im][jn][2] * 0.125f) * ivB : 0.f;
                float e3 = ((wB >> (bi + 1)) & 1u) ? __expf(acc[im][jn][3] * 0.125f) * ivB : 0.f;
                *(float2*)&stage[rAl * 68 + bp] = make_float2(e0, e1);
                *(float2*)&stage[rBl * 68 + bp] = make_float2(e2, e3);
            }
        }
        __syncthreads();

        // --- AV MMA: O += P(stage) * V(Vs) ---
#pragma unroll
        for (int ks = 0; ks < 8; ks++) {
            const int kk = ks * 8;
            uint32_t af[4][4], bf[2][2];
#pragma unroll
            for (int im = 0; im < 4; im++)
                ldsm_x4(af[im], StU + (uint32_t)(rowQ[im] + kk) * 4);
#pragma unroll
            for (int jd = 0; jd < 2; jd++)
                ldsm_x2(bf[jd], VsU + (uint32_t)(rowV[jd] + kk) * 4);
#pragma unroll
            for (int im = 0; im < 4; im++)
#pragma unroll
                for (int jd = 0; jd < 2; jd++)
                    MMA_TF32(accO[im][jd], af[im][0], af[im][1], af[im][2], af[im][3],
                             bf[jd][0], bf[jd][1]);
        }

        // --- coalesced attn write from stage (exact fp32 values) ---
        float* abase = attn + ((size_t)(bh * SS + q0)) * SS + k0;
#pragma unroll
        for (int j = 0; j < 8; j++) {
            int idx = tid + j * 256;          // 0..2047 float4
            int r = idx >> 4, c4 = (idx & 15) * 4;
            float4 v = *(float4*)&stage[r * 68 + c4];
            *(float4*)(abase + (size_t)r * SS + c4) = v;
        }
    }

    // --- O epilogue ---
#pragma unroll
    for (int im = 0; im < 4; im++) {
        const int rowAo = q0 + wm * 64 + im * 16 + g;
        const int rowBo = rowAo + 8;
#pragma unroll
        for (int jd = 0; jd < 2; jd++) {
            const int col = h * HDD + wn * 16 + jd * 8 + 2 * t;
            *(float2*)(Ob + (size_t)(b * SS + rowAo) * HH + col) =
                make_float2(accO[im][jd][0], accO[im][jd][1]);
            *(float2*)(Ob + (size_t)(b * SS + rowBo) * HH + col) =
                make_float2(accO[im][jd][2], accO[im][jd][3]);
        }
    }
}

// ============================================================
// LayerNorm
// ============================================================
__global__ void ln_kernel(const float* __restrict__ X,
                          const float* __restrict__ w,
                          const float* __restrict__ bias,
                          float* __restrict__ Y) {
    __shared__ float red[8];
    __shared__ float bc;
    const int row = blockIdx.x;
    const float* x = X + (size_t)row * HH;
    const int tid = threadIdx.x, lane = tid & 31, warp = tid >> 5;

    float s = 0.f;
    for (int c = tid; c < HH; c += 256) s += x[c];
#pragma unroll
    for (int o = 16; o; o >>= 1) s += __shfl_xor_sync(0xffffffffu, s, o);
    if (lane == 0) red[warp] = s;
    __syncthreads();
    if (tid == 0) {
        float tt = 0.f;
        for (int i = 0; i < 8; i++) tt += red[i];
        bc = tt / HH;
    }
    __syncthreads();
    float mu = bc;

    float v = 0.f;
    for (int c = tid; c < HH; c += 256) { float d = x[c] - mu; v += d * d; }
#pragma unroll
    for (int o = 16; o; o >>= 1) v += __shfl_xor_sync(0xffffffffu, v, o);
    if (lane == 0) red[warp] = v;
    __syncthreads();
    if (tid == 0) {
        float tt = 0.f;
        for (int i = 0; i < 8; i++) tt += red[i];
        bc = rsqrtf(tt / HH + 1e-6f);
    }
    __syncthreads();
    float inv = bc;

    for (int c = tid; c < HH; c += 256)
        Y[(size_t)row * HH + c] = (x[c] - mu) * inv * w[c] + bias[c];
}

// ============================================================
extern "C" void kernel_launch(void* const* d_in, const int* in_sizes, int n_in,
                              void* d_out, int out_size) {
    const float* enc  = (const float*)d_in[0];
    const float* mask = (const float*)d_in[1];
    const float* WQ   = (const float*)d_in[2];
    const float* WK   = (const float*)d_in[3];
    const float* WV   = (const float*)d_in[4];
    const float* WO   = (const float*)d_in[5];
    const float* lnw  = (const float*)d_in[6];
    const float* lnb  = (const float*)d_in[7];

    float* y    = (float*)d_out;              // (B,S,H)
    float* attn = y + (size_t)Y_SIZE;         // (B,NH,S,S)

    float *Qp, *Kp, *Vp, *Op, *Xp, *Ip;
    unsigned int* Mp;
    cudaGetSymbolAddress((void**)&Qp, g_Q);
    cudaGetSymbolAddress((void**)&Kp, g_K);
    cudaGetSymbolAddress((void**)&Vp, g_V);
    cudaGetSymbolAddress((void**)&Op, g_AO);
    cudaGetSymbolAddress((void**)&Xp, g_X);
    cudaGetSymbolAddress((void**)&Ip, g_INV);
    cudaGetSymbolAddress((void**)&Mp, g_MB);

    maskbits_kernel<<<BB*SS*SS/256, 256>>>(mask, Mp);

    dim3 gt(HH / 128, MM / 128);   // (8, 32)
    gemm_mma_kernel<<<gt, 256>>>(enc, WQ, Qp, nullptr);
    gemm_mma_kernel<<<gt, 256>>>(enc, WK, Kp, nullptr);
    gemm_mma_kernel<<<gt, 256>>>(enc, WV, Vp, nullptr);

    const int inv_smem = 13824 * (int)sizeof(float);   // 55296
    cudaFuncSetAttribute(inv_kernel,
                         cudaFuncAttributeMaxDynamicSharedMemorySize, inv_smem);
    inv_kernel<<<dim3(SS / 128, BB * NHH), 256, inv_smem>>>(Qp, Kp, Mp, Ip);

    const int fa_smem = 26496 * (int)sizeof(float);    // 105984
    cudaFuncSetAttribute(fused_attn_kernel,
                         cudaFuncAttributeMaxDynamicSharedMemorySize, fa_smem);
    fused_attn_kernel<<<dim3(SS / 128, BB * NHH), 256, fa_smem>>>(Qp, Kp, Vp, Mp, Ip, attn, Op);

    gemm_mma_kernel<<<gt, 256>>>(Op, WO, Xp, enc);

    ln_kernel<<<MM, 256>>>(Xp, lnw, lnb, y);
}

// round 11
// speedup vs baseline: 1.1997x; 1.0172x over previous
#include <cuda_runtime.h>
#include <math.h>
#include <stdint.h>

#define BB 2
#define SS 2048
#define HH 1024
#define NHH 16
#define HDD 64
#define MM (BB*SS)          // 4096
#define Y_SIZE (BB*SS*HH)   // 4194304
#define NROWS (BB*NHH*SS)   // 65536

// ---- scratch (no allocation allowed; device globals) ----
__device__ float g_Q[MM*HH];
__device__ float g_K[MM*HH];
__device__ float g_V[MM*HH];
__device__ float g_AO[MM*HH];
__device__ float g_X[MM*HH];
__device__ float g_INV[NROWS];              // 1/rowsum
__device__ unsigned int g_MB[BB*SS*SS/32];  // mask bits

__device__ __forceinline__ uint32_t f2tf32(float v) {
    uint32_t r;
    asm("cvt.rna.tf32.f32 %0, %1;" : "=r"(r) : "f"(v));
    return r;
}

#define MMA_TF32(acc, a0,a1,a2,a3, b0,b1) \
    asm volatile("mma.sync.aligned.m16n8k8.row.col.f32.tf32.tf32.f32 " \
        "{%0,%1,%2,%3}, {%4,%5,%6,%7}, {%8,%9}, {%0,%1,%2,%3};" \
        : "+f"((acc)[0]), "+f"((acc)[1]), "+f"((acc)[2]), "+f"((acc)[3]) \
        : "r"(a0), "r"(a1), "r"(a2), "r"(a3), "r"(b0), "r"(b1))

__device__ __forceinline__ void ldsm_x4(uint32_t* r, uint32_t addr) {
    asm volatile("ldmatrix.sync.aligned.m8n8.x4.shared.b16 {%0,%1,%2,%3}, [%4];"
        : "=r"(r[0]), "=r"(r[1]), "=r"(r[2]), "=r"(r[3]) : "r"(addr));
}
__device__ __forceinline__ void ldsm_x2(uint32_t* r, uint32_t addr) {
    asm volatile("ldmatrix.sync.aligned.m8n8.x2.shared.b16 {%0,%1}, [%2];"
        : "=r"(r[0]), "=r"(r[1]) : "r"(addr));
}
#define LDSM_SELS() \
    const int rsel = (lane & 7) + ((lane >> 3) & 1) * 8; \
    const int cA = (lane >> 4) * 4; \
    const int rB = lane & 7; \
    const int cB = ((lane >> 3) & 1) * 4;

// ============================================================
// mask (B,1,S,S) float -> bit per element
// ============================================================
__global__ void __launch_bounds__(256)
maskbits_kernel(const float* __restrict__ mask, unsigned int* __restrict__ mb) {
    int i = blockIdx.x * 256 + threadIdx.x;
    float m = mask[i];
    unsigned int bal = __ballot_sync(0xffffffffu, m != 0.f);
    if ((threadIdx.x & 31) == 0) mb[i >> 5] = bal;
}

// ============================================================
// GEMM body shared by qkv (rounded epilogue, no res) and WO (res add).
// smem stores use cvt.rna.tf32 (RNA; truncation is biased -> 2e-3 fail).
// ============================================================
#define GEMM_BODY(A_, W_, EPILOGUE)                                            \
    __shared__ float As[2][128 * 20];                                          \
    __shared__ float Ws[2][128 * 20];                                          \
    const int tid = threadIdx.x;                                               \
    const int wid = tid >> 5, lane = tid & 31;                                 \
    const int wm = wid >> 2, wn = wid & 3;                                     \
    const int bm = blockIdx.y * 128, bn = blockIdx.x * 128;                    \
    LDSM_SELS();                                                               \
    const uint32_t AsU = (uint32_t)__cvta_generic_to_shared(&As[0][0]);        \
    const uint32_t WsU = (uint32_t)__cvta_generic_to_shared(&Ws[0][0]);        \
    int rowA[4], rowB[4];                                                      \
    for (int im = 0; im < 4; im++) rowA[im] = (wm*64 + im*16 + rsel)*20 + cA;  \
    for (int jn = 0; jn < 4; jn++) rowB[jn] = (wn*32 + jn*8 + rB)*20 + cB;     \
    const int p0 = tid, p1 = tid + 256;                                        \
    const int r0 = p0 >> 2, q0 = (p0 & 3) * 4;                                 \
    const int r1 = p1 >> 2, q1 = (p1 & 3) * 4;                                 \
    const float* Arow0 = A_ + (size_t)(bm + r0) * 1024 + q0;                   \
    const float* Arow1 = A_ + (size_t)(bm + r1) * 1024 + q1;                   \
    const float* Wrow0 = W_ + (size_t)(bn + r0) * 1024 + q0;                   \
    const float* Wrow1 = W_ + (size_t)(bn + r1) * 1024 + q1;                   \
    const int s0 = r0 * 20 + q0, s1 = r1 * 20 + q1;                            \
    float acc[4][4][4];                                                        \
    for (int i = 0; i < 4; i++)                                                \
        for (int j = 0; j < 4; j++)                                            \
            for (int q = 0; q < 4; q++) acc[i][j][q] = 0.f;                    \
    {                                                                          \
        float4 va0 = *(const float4*)(Arow0);                                  \
        float4 va1 = *(const float4*)(Arow1);                                  \
        float4 vw0 = *(const float4*)(Wrow0);                                  \
        float4 vw1 = *(const float4*)(Wrow1);                                  \
        uint32_t* a0 = (uint32_t*)&As[0][s0];                                  \
        a0[0]=f2tf32(va0.x); a0[1]=f2tf32(va0.y); a0[2]=f2tf32(va0.z); a0[3]=f2tf32(va0.w); \
        uint32_t* a1 = (uint32_t*)&As[0][s1];                                  \
        a1[0]=f2tf32(va1.x); a1[1]=f2tf32(va1.y); a1[2]=f2tf32(va1.z); a1[3]=f2tf32(va1.w); \
        uint32_t* w0 = (uint32_t*)&Ws[0][s0];                                  \
        w0[0]=f2tf32(vw0.x); w0[1]=f2tf32(vw0.y); w0[2]=f2tf32(vw0.z); w0[3]=f2tf32(vw0.w); \
        uint32_t* w1 = (uint32_t*)&Ws[0][s1];                                  \
        w1[0]=f2tf32(vw1.x); w1[1]=f2tf32(vw1.y); w1[2]=f2tf32(vw1.z); w1[3]=f2tf32(vw1.w); \
    }                                                                          \
    __syncthreads();                                                           \
    for (int c = 0; c < 64; c++) {                                             \
        const int buf = c & 1;                                                 \
        const uint32_t aBuf = AsU + (uint32_t)buf * (128 * 20 * 4);            \
        const uint32_t wBuf = WsU + (uint32_t)buf * (128 * 20 * 4);            \
        float4 ra0, ra1, rw0, rw1;                                             \
        if (c < 63) {                                                          \
            const int k0 = (c + 1) * 16;                                       \
            ra0 = *(const float4*)(Arow0 + k0);                                \
            ra1 = *(const float4*)(Arow1 + k0);                                \
            rw0 = *(const float4*)(Wrow0 + k0);                                \
            rw1 = *(const float4*)(Wrow1 + k0);                                \
        }                                                                      \
        for (int ks = 0; ks < 2; ks++) {                                       \
            const int kk = ks * 8;                                             \
            uint32_t af[4][4], bf[4][2];                                       \
            for (int im = 0; im < 4; im++)                                     \
                ldsm_x4(af[im], aBuf + (uint32_t)(rowA[im] + kk) * 4);         \
            for (int jn = 0; jn < 4; jn++)                                     \
                ldsm_x2(bf[jn], wBuf + (uint32_t)(rowB[jn] + kk) * 4);         \
            for (int im = 0; im < 4; im++)                                     \
                for (int jn = 0; jn < 4; jn++)                                 \
                    MMA_TF32(acc[im][jn], af[im][0], af[im][1], af[im][2], af[im][3], \
                             bf[jn][0], bf[jn][1]);                            \
        }                                                                      \
        if (c < 63) {                                                          \
            const int nxt = buf ^ 1;                                           \
            uint32_t* a0 = (uint32_t*)&As[nxt][s0];                            \
            a0[0]=f2tf32(ra0.x); a0[1]=f2tf32(ra0.y); a0[2]=f2tf32(ra0.z); a0[3]=f2tf32(ra0.w); \
            uint32_t* a1 = (uint32_t*)&As[nxt][s1];                            \
            a1[0]=f2tf32(ra1.x); a1[1]=f2tf32(ra1.y); a1[2]=f2tf32(ra1.z); a1[3]=f2tf32(ra1.w); \
            uint32_t* w0 = (uint32_t*)&Ws[nxt][s0];                            \
            w0[0]=f2tf32(rw0.x); w0[1]=f2tf32(rw0.y); w0[2]=f2tf32(rw0.z); w0[3]=f2tf32(rw0.w); \
            uint32_t* w1 = (uint32_t*)&Ws[nxt][s1];                            \
            w1[0]=f2tf32(rw1.x); w1[1]=f2tf32(rw1.y); w1[2]=f2tf32(rw1.z); w1[3]=f2tf32(rw1.w); \
        }                                                                      \
        __syncthreads();                                                       \
    }                                                                          \
    const int g = lane >> 2, t = lane & 3;                                     \
    EPILOGUE

// QKV: one launch, grid.z selects weight/output; epilogue PRE-ROUNDS to tf32.
__global__ void __launch_bounds__(256, 2)
qkv_gemm_kernel(const float* __restrict__ enc,
                const float* __restrict__ WQ, const float* __restrict__ WK,
                const float* __restrict__ WV,
                float* __restrict__ Qo, float* __restrict__ Ko, float* __restrict__ Vo) {
    const int z = blockIdx.z;
    const float* Wsel = (z == 0) ? WQ : (z == 1) ? WK : WV;
    float* Csel = (z == 0) ? Qo : (z == 1) ? Ko : Vo;
    GEMM_BODY(enc, Wsel,
        {
            for (int im = 0; im < 4; im++) {
                const int rowAo = bm + wm * 64 + im * 16 + g;
                const int rowBo = rowAo + 8;
                for (int jn = 0; jn < 4; jn++) {
                    const int col = bn + wn * 32 + jn * 8 + 2 * t;
                    float2 vA = make_float2(__uint_as_float(f2tf32(acc[im][jn][0])),
                                            __uint_as_float(f2tf32(acc[im][jn][1])));
                    float2 vB = make_float2(__uint_as_float(f2tf32(acc[im][jn][2])),
                                            __uint_as_float(f2tf32(acc[im][jn][3])));
                    *(float2*)(Csel + (size_t)rowAo * 1024 + col) = vA;
                    *(float2*)(Csel + (size_t)rowBo * 1024 + col) = vB;
                }
            }
        })
}

// WO: residual-add epilogue, full fp32 output.
__global__ void __launch_bounds__(256, 2)
gemm_res_kernel(const float* __restrict__ A, const float* __restrict__ W,
                float* __restrict__ C, const float* __restrict__ res) {
    GEMM_BODY(A, W,
        {
            for (int im = 0; im < 4; im++) {
                const int rowAo = bm + wm * 64 + im * 16 + g;
                const int rowBo = rowAo + 8;
                for (int jn = 0; jn < 4; jn++) {
                    const int col = bn + wn * 32 + jn * 8 + 2 * t;
                    float2 rA = *(const float2*)(res + (size_t)rowAo * 1024 + col);
                    float2 rB2 = *(const float2*)(res + (size_t)rowBo * 1024 + col);
                    *(float2*)(C + (size_t)rowAo * 1024 + col) =
                        make_float2(acc[im][jn][0] + rA.x, acc[im][jn][1] + rA.y);
                    *(float2*)(C + (size_t)rowBo * 1024 + col) =
                        make_float2(acc[im][jn][2] + rB2.x, acc[im][jn][3] + rB2.y);
                }
            }
        })
}

// ============================================================
// Pass A: inv[row] = 1/sum_k (mask ? exp(q.k/8) : 0).
// Q/K pre-rounded tf32 -> raw loads. K+mask prefetched one tile ahead.
// ============================================================
__global__ void __launch_bounds__(256, 2)
inv_kernel(const float* __restrict__ Qb, const float* __restrict__ Kb,
           const unsigned int* __restrict__ mb, float* __restrict__ invs) {
    extern __shared__ float sm[];
    float* Qs = sm;
    float* Ks = sm + 8704;
    float* sumbuf = sm + 13056;
    unsigned int* maskS = (unsigned int*)(sm + 13568);

    const int tid = threadIdx.x;
    const int wid = tid >> 5, lane = tid & 31;
    const int wm = wid >> 2, wn = wid & 3;
    const int bh = blockIdx.y, b = bh >> 4, h = bh & 15;
    const int q0 = blockIdx.x * 128;
    LDSM_SELS();
    const int g = lane >> 2, t = lane & 3;

    const uint32_t QsU = (uint32_t)__cvta_generic_to_shared(Qs);
    const uint32_t KsU = (uint32_t)__cvta_generic_to_shared(Ks);
    int rowA[4], rowBr[2];
#pragma unroll
    for (int im = 0; im < 4; im++) rowA[im] = (wm * 64 + im * 16 + rsel) * 68 + cA;
#pragma unroll
    for (int jn = 0; jn < 2; jn++) rowBr[jn] = (wn * 16 + jn * 8 + rB) * 68 + cB;

    const float* Qbase = Qb + ((size_t)(b * SS + q0)) * HH + h * HDD;
    const float* Kbase = Kb + ((size_t)b * SS) * HH + h * HDD;
    const int lr = tid >> 4, lc4 = (tid & 15) * 4;     // K-load row/col per thread
    const int mr = tid >> 1, mw = tid & 1;             // mask word per thread
#pragma unroll
    for (int j = 0; j < 8; j++) {
        int idx = tid + j * 256;
        int r = idx >> 4, c4 = (idx & 15) * 4;
        *(float4*)&Qs[r * 68 + c4] = *(const float4*)(Qbase + (size_t)r * HH + c4);
    }
    // tile 0
    {
#pragma unroll
        for (int j = 0; j < 4; j++) {
            int r = lr + j * 16;
            *(float4*)&Ks[r * 68 + lc4] = *(const float4*)(Kbase + (size_t)r * HH + lc4);
        }
        maskS[tid] = mb[(size_t)(b * SS + q0 + mr) * 64 + mw];
    }
    __syncthreads();

    float rsA[4], rsB[4];
#pragma unroll
    for (int im = 0; im < 4; im++) { rsA[im] = 0.f; rsB[im] = 0.f; }

    for (int kt = 0; kt < 32; kt++) {
        const bool pf = (kt < 31);
        float4 rk[4];
        unsigned int rm = 0;
        if (pf) {
            const int n1 = (kt + 1) * 64;
#pragma unroll
            for (int j = 0; j < 4; j++)
                rk[j] = *(const float4*)(Kbase + (size_t)(n1 + lr + j * 16) * HH + lc4);
            rm = mb[(size_t)(b * SS + q0 + mr) * 64 + (n1 >> 5) + mw];
        }

        float acc[4][2][4];
#pragma unroll
        for (int i = 0; i < 4; i++)
#pragma unroll
            for (int j = 0; j < 2; j++)
#pragma unroll
                for (int q = 0; q < 4; q++) acc[i][j][q] = 0.f;
#pragma unroll
        for (int ks = 0; ks < 8; ks++) {
            const int kk = ks * 8;
            uint32_t af[4][4], bf[2][2];
#pragma unroll
            for (int im = 0; im < 4; im++)
                ldsm_x4(af[im], QsU + (uint32_t)(rowA[im] + kk) * 4);
#pragma unroll
            for (int jn = 0; jn < 2; jn++)
                ldsm_x2(bf[jn], KsU + (uint32_t)(rowBr[jn] + kk) * 4);
#pragma unroll
            for (int im = 0; im < 4; im++)
#pragma unroll
                for (int jn = 0; jn < 2; jn++)
                    MMA_TF32(acc[im][jn], af[im][0], af[im][1], af[im][2], af[im][3],
                             bf[jn][0], bf[jn][1]);
        }

#pragma unroll
        for (int im = 0; im < 4; im++) {
            const int rAl = wm * 64 + im * 16 + g;
            const int rBl = rAl + 8;
#pragma unroll
            for (int jn = 0; jn < 2; jn++) {
                const int bp = wn * 16 + jn * 8 + 2 * t;
                const unsigned int wA = maskS[rAl * 2 + (bp >> 5)];
                const unsigned int wB = maskS[rBl * 2 + (bp >> 5)];
                const int bi = bp & 31;
                if ((wA >> bi) & 1u)       rsA[im] += __expf(acc[im][jn][0] * 0.125f);
                if ((wA >> (bi + 1)) & 1u) rsA[im] += __expf(acc[im][jn][1] * 0.125f);
                if ((wB >> bi) & 1u)       rsB[im] += __expf(acc[im][jn][2] * 0.125f);
                if ((wB >> (bi + 1)) & 1u) rsB[im] += __expf(acc[im][jn][3] * 0.125f);
            }
        }
        __syncthreads();
        if (pf) {
#pragma unroll
            for (int j = 0; j < 4; j++)
                *(float4*)&Ks[(lr + j * 16) * 68 + lc4] = rk[j];
            maskS[tid] = rm;
        }
        __syncthreads();
    }

#pragma unroll
    for (int im = 0; im < 4; im++) {
        float a = rsA[im], bb = rsB[im];
        a += __shfl_xor_sync(0xffffffffu, a, 1);
        a += __shfl_xor_sync(0xffffffffu, a, 2);
        bb += __shfl_xor_sync(0xffffffffu, bb, 1);
        bb += __shfl_xor_sync(0xffffffffu, bb, 2);
        if (t == 0) {
            sumbuf[(wm * 64 + im * 16 + g) * 4 + wn] = a;
            sumbuf[(wm * 64 + im * 16 + g + 8) * 4 + wn] = bb;
        }
    }
    __syncthreads();
    if (tid < 128) {
        float s = sumbuf[tid * 4] + sumbuf[tid * 4 + 1] +
                  sumbuf[tid * 4 + 2] + sumbuf[tid * 4 + 3];
        invs[(size_t)bh * SS + q0 + tid] = (s > 0.f) ? 1.f / s : 0.f;
    }
}

// ============================================================
// Pass B: fused attn + AV. Raw loads (pre-rounded Q/K/V), fp32 attn staging.
// K+mask prefetched at loop top; V(kt+1) prefetched during AV phase.
// ============================================================
__global__ void __launch_bounds__(256, 2)
fused_attn_kernel(const float* __restrict__ Qb, const float* __restrict__ Kb,
                  const float* __restrict__ Vb, const unsigned int* __restrict__ mb,
                  const float* __restrict__ invs,
                  float* __restrict__ attn, float* __restrict__ Ob) {
    extern __shared__ float sm[];
    float* Qs = sm;
    float* Ks = sm + 8704;
    float* Vs = sm + 13056;
    float* stage = sm + 17408;
    unsigned int* maskS = (unsigned int*)(sm + 26112);
    float* invS = sm + 26368;

    const int tid = threadIdx.x;
    const int wid = tid >> 5, lane = tid & 31;
    const int wm = wid >> 2, wn = wid & 3;
    const int bh = blockIdx.y, b = bh >> 4, h = bh & 15;
    const int q0 = blockIdx.x * 128;
    LDSM_SELS();
    const int g = lane >> 2, t = lane & 3;

    const uint32_t QsU = (uint32_t)__cvta_generic_to_shared(Qs);
    const uint32_t KsU = (uint32_t)__cvta_generic_to_shared(Ks);
    const uint32_t VsU = (uint32_t)__cvta_generic_to_shared(Vs);
    const uint32_t StU = (uint32_t)__cvta_generic_to_shared(stage);

    int rowQ[4], rowK[2], rowV[2];
#pragma unroll
    for (int im = 0; im < 4; im++) rowQ[im] = (wm * 64 + im * 16 + rsel) * 68 + cA;
#pragma unroll
    for (int jn = 0; jn < 2; jn++) rowK[jn] = (wn * 16 + jn * 8 + rB) * 68 + cB;
#pragma unroll
    for (int jd = 0; jd < 2; jd++) rowV[jd] = (wn * 16 + jd * 8 + rB) * 68 + cB;

    const float* Qbase = Qb + ((size_t)(b * SS + q0)) * HH + h * HDD;
    const float* Kbase = Kb + ((size_t)b * SS) * HH + h * HDD;
    const float* Vbase = Vb + ((size_t)b * SS) * HH + h * HDD;
    const int lr = tid >> 4, lc4 = (tid & 15) * 4;
    const int mr = tid >> 1, mw = tid & 1;

#pragma unroll
    for (int j = 0; j < 8; j++) {
        int idx = tid + j * 256;
        int r = idx >> 4, c4 = (idx & 15) * 4;
        *(float4*)&Qs[r * 68 + c4] = *(const float4*)(Qbase + (size_t)r * HH + c4);
    }
    if (tid < 128) invS[tid] = invs[(size_t)bh * SS + q0 + tid];
    // tile 0
    {
#pragma unroll
        for (int j = 0; j < 4; j++) {
            int r = lr + j * 16;
            *(float4*)&Ks[r * 68 + lc4] = *(const float4*)(Kbase + (size_t)r * HH + lc4);
            float4 vv = *(const float4*)(Vbase + (size_t)r * HH + lc4);
            Vs[(lc4 + 0) * 68 + r] = vv.x;
            Vs[(lc4 + 1) * 68 + r] = vv.y;
            Vs[(lc4 + 2) * 68 + r] = vv.z;
            Vs[(lc4 + 3) * 68 + r] = vv.w;
        }
        maskS[tid] = mb[(size_t)(b * SS + q0 + mr) * 64 + mw];
    }
    __syncthreads();

    float accO[4][2][4];
#pragma unroll
    for (int i = 0; i < 4; i++)
#pragma unroll
        for (int j = 0; j < 2; j++)
#pragma unroll
            for (int q = 0; q < 4; q++) accO[i][j][q] = 0.f;

    for (int kt = 0; kt < 32; kt++) {
        const int k0 = kt * 64;
        const bool pf = (kt < 31);
        // prefetch K(kt+1) + mask(kt+1) (in flight across QK phase)
        float4 rk[4];
        unsigned int rm = 0;
        if (pf) {
#pragma unroll
            for (int j = 0; j < 4; j++)
                rk[j] = *(const float4*)(Kbase + (size_t)(k0 + 64 + lr + j * 16) * HH + lc4);
            rm = mb[(size_t)(b * SS + q0 + mr) * 64 + ((k0 + 64) >> 5) + mw];
        }

        // --- S = Q K^T ---
        float acc[4][2][4];
#pragma unroll
        for (int i = 0; i < 4; i++)
#pragma unroll
            for (int j = 0; j < 2; j++)
#pragma unroll
                for (int q = 0; q < 4; q++) acc[i][j][q] = 0.f;
#pragma unroll
        for (int ks = 0; ks < 8; ks++) {
            const int kk = ks * 8;
            uint32_t af[4][4], bf[2][2];
#pragma unroll
            for (int im = 0; im < 4; im++)
                ldsm_x4(af[im], QsU + (uint32_t)(rowQ[im] + kk) * 4);
#pragma unroll
            for (int jn = 0; jn < 2; jn++)
                ldsm_x2(bf[jn], KsU + (uint32_t)(rowK[jn] + kk) * 4);
#pragma unroll
            for (int im = 0; im < 4; im++)
#pragma unroll
                for (int jn = 0; jn < 2; jn++)
                    MMA_TF32(acc[im][jn], af[im][0], af[im][1], af[im][2], af[im][3],
                             bf[jn][0], bf[jn][1]);
        }

        // --- attn = mask ? exp(S/8)*inv : 0 -> stage (fp32) ---
#pragma unroll
        for (int im = 0; im < 4; im++) {
            const int rAl = wm * 64 + im * 16 + g;
            const int rBl = rAl + 8;
            const float ivA = invS[rAl], ivB = invS[rBl];
#pragma unroll
            for (int jn = 0; jn < 2; jn++) {
                const int bp = wn * 16 + jn * 8 + 2 * t;
                const unsigned int wA = maskS[rAl * 2 + (bp >> 5)];
                const unsigned int wB = maskS[rBl * 2 + (bp >> 5)];
                const int bi = bp & 31;
                float e0 = ((wA >> bi) & 1u)       ? __expf(acc[im][jn][0] * 0.125f) * ivA : 0.f;
                float e1 = ((wA >> (bi + 1)) & 1u) ? __expf(acc[im][jn][1] * 0.125f) * ivA : 0.f;
                float e2 = ((wB >> bi) & 1u)       ? __expf(acc[im][jn][2] * 0.125f) * ivB : 0.f;
                float e3 = ((wB >> (bi + 1)) & 1u) ? __expf(acc[im][jn][3] * 0.125f) * ivB : 0.f;
                *(float2*)&stage[rAl * 68 + bp] = make_float2(e0, e1);
                *(float2*)&stage[rBl * 68 + bp] = make_float2(e2, e3);
            }
        }
        // prefetch V(kt+1) (in flight across AV phase)
        float4 rv[4];
        if (pf) {
#pragma unroll
            for (int j = 0; j < 4; j++)
                rv[j] = *(const float4*)(Vbase + (size_t)(k0 + 64 + lr + j * 16) * HH + lc4);
        }
        __syncthreads();    // A: stage visible; QK done reading Ks

        // --- AV MMA: O += P(stage) * V(Vs) ---
#pragma unroll
        for (int ks = 0; ks < 8; ks++) {
            const int kk = ks * 8;
            uint32_t af[4][4], bf[2][2];
#pragma unroll
            for (int im = 0; im < 4; im++)
                ldsm_x4(af[im], StU + (uint32_t)(rowQ[im] + kk) * 4);
#pragma unroll
            for (int jd = 0; jd < 2; jd++)
                ldsm_x2(bf[jd], VsU + (uint32_t)(rowV[jd] + kk) * 4);
#pragma unroll
            for (int im = 0; im < 4; im++)
#pragma unroll
                for (int jd = 0; jd < 2; jd++)
                    MMA_TF32(accO[im][jd], af[im][0], af[im][1], af[im][2], af[im][3],
                             bf[jd][0], bf[jd][1]);
        }

        // --- coalesced attn write from stage ---
        float* abase = attn + ((size_t)(bh * SS + q0)) * SS + k0;
#pragma unroll
        for (int j = 0; j < 8; j++) {
            int idx = tid + j * 256;
            int r = idx >> 4, c4 = (idx & 15) * 4;
            float4 v = *(float4*)&stage[r * 68 + c4];
            *(float4*)(abase + (size_t)r * SS + c4) = v;
        }
        __syncthreads();    // B: Ks/Vs/maskS free
        if (pf) {
#pragma unroll
            for (int j = 0; j < 4; j++) {
                int r = lr + j * 16;
                *(float4*)&Ks[r * 68 + lc4] = rk[j];
                Vs[(lc4 + 0) * 68 + r] = rv[j].x;
                Vs[(lc4 + 1) * 68 + r] = rv[j].y;
                Vs[(lc4 + 2) * 68 + r] = rv[j].z;
                Vs[(lc4 + 3) * 68 + r] = rv[j].w;
            }
            maskS[tid] = rm;
        }
        __syncthreads();    // C: next tile ready
    }

    // --- O epilogue ---
#pragma unroll
    for (int im = 0; im < 4; im++) {
        const int rowAo = q0 + wm * 64 + im * 16 + g;
        const int rowBo = rowAo + 8;
#pragma unroll
        for (int jd = 0; jd < 2; jd++) {
            const int col = h * HDD + wn * 16 + jd * 8 + 2 * t;
            *(float2*)(Ob + (size_t)(b * SS + rowAo) * HH + col) =
                make_float2(accO[im][jd][0], accO[im][jd][1]);
            *(float2*)(Ob + (size_t)(b * SS + rowBo) * HH + col) =
                make_float2(accO[im][jd][2], accO[im][jd][3]);
        }
    }
}

// ============================================================
// LayerNorm
// ============================================================
__global__ void ln_kernel(const float* __restrict__ X,
                          const float* __restrict__ w,
                          const float* __restrict__ bias,
                          float* __restrict__ Y) {
    __shared__ float red[8];
    __shared__ float bc;
    const int row = blockIdx.x;
    const float* x = X + (size_t)row * HH;
    const int tid = threadIdx.x, lane = tid & 31, warp = tid >> 5;

    float s = 0.f;
    for (int c = tid; c < HH; c += 256) s += x[c];
#pragma unroll
    for (int o = 16; o; o >>= 1) s += __shfl_xor_sync(0xffffffffu, s, o);
    if (lane == 0) red[warp] = s;
    __syncthreads();
    if (tid == 0) {
        float tt = 0.f;
        for (int i = 0; i < 8; i++) tt += red[i];
        bc = tt / HH;
    }
    __syncthreads();
    float mu = bc;

    float v = 0.f;
    for (int c = tid; c < HH; c += 256) { float d = x[c] - mu; v += d * d; }
#pragma unroll
    for (int o = 16; o; o >>= 1) v += __shfl_xor_sync(0xffffffffu, v, o);
    if (lane == 0) red[warp] = v;
    __syncthreads();
    if (tid == 0) {
        float tt = 0.f;
        for (int i = 0; i < 8; i++) tt += red[i];
        bc = rsqrtf(tt / HH + 1e-6f);
    }
    __syncthreads();
    float inv = bc;

    for (int c = tid; c < HH; c += 256)
        Y[(size_t)row * HH + c] = (x[c] - mu) * inv * w[c] + bias[c];
}

// ============================================================
extern "C" void kernel_launch(void* const* d_in, const int* in_sizes, int n_in,
                              void* d_out, int out_size) {
    const float* enc  = (const float*)d_in[0];
    const float* mask = (const float*)d_in[1];
    const float* WQ   = (const float*)d_in[2];
    const float* WK   = (const float*)d_in[3];
    const float* WV   = (const float*)d_in[4];
    const float* WO   = (const float*)d_in[5];
    const float* lnw  = (const float*)d_in[6];
    const float* lnb  = (const float*)d_in[7];

    float* y    = (float*)d_out;              // (B,S,H)
    float* attn = y + (size_t)Y_SIZE;         // (B,NH,S,S)

    float *Qp, *Kp, *Vp, *Op, *Xp, *Ip;
    unsigned int* Mp;
    cudaGetSymbolAddress((void**)&Qp, g_Q);
    cudaGetSymbolAddress((void**)&Kp, g_K);
    cudaGetSymbolAddress((void**)&Vp, g_V);
    cudaGetSymbolAddress((void**)&Op, g_AO);
    cudaGetSymbolAddress((void**)&Xp, g_X);
    cudaGetSymbolAddress((void**)&Ip, g_INV);
    cudaGetSymbolAddress((void**)&Mp, g_MB);

    maskbits_kernel<<<BB*SS*SS/256, 256>>>(mask, Mp);

    qkv_gemm_kernel<<<dim3(HH / 128, MM / 128, 3), 256>>>(enc, WQ, WK, WV, Qp, Kp, Vp);

    const int inv_smem = 13824 * (int)sizeof(float);   // 55296
    cudaFuncSetAttribute(inv_kernel,
                         cudaFuncAttributeMaxDynamicSharedMemorySize, inv_smem);
    inv_kernel<<<dim3(SS / 128, BB * NHH), 256, inv_smem>>>(Qp, Kp, Mp, Ip);

    const int fa_smem = 26496 * (int)sizeof(float);    // 105984
    cudaFuncSetAttribute(fused_attn_kernel,
                         cudaFuncAttributeMaxDynamicSharedMemorySize, fa_smem);
    fused_attn_kernel<<<dim3(SS / 128, BB * NHH), 256, fa_smem>>>(Qp, Kp, Vp, Mp, Ip, attn, Op);

    gemm_res_kernel<<<dim3(HH / 128, MM / 128), 256>>>(Op, WO, Xp, enc);

    ln_kernel<<<MM, 256>>>(Xp, lnw, lnb, y);
}

// round 12
// speedup vs baseline: 1.2647x; 1.0542x over previous
#include <cuda_runtime.h>
#include <math.h>
#include <stdint.h>

#define BB 2
#define SS 2048
#define HH 1024
#define NHH 16
#define HDD 64
#define MM (BB*SS)          // 4096
#define Y_SIZE (BB*SS*HH)   // 4194304
#define NROWS (BB*NHH*SS)   // 65536

// ---- scratch (no allocation allowed; device globals) ----
__device__ float g_Q[MM*HH];
__device__ float g_K[MM*HH];
__device__ float g_V[MM*HH];
__device__ float g_AO[MM*HH];
__device__ float g_X[MM*HH];
__device__ unsigned int g_MB[BB*SS*SS/32];  // mask bits

__device__ __forceinline__ uint32_t f2tf32(float v) {
    uint32_t r;
    asm("cvt.rna.tf32.f32 %0, %1;" : "=r"(r) : "f"(v));
    return r;
}

#define MMA_TF32(acc, a0,a1,a2,a3, b0,b1) \
    asm volatile("mma.sync.aligned.m16n8k8.row.col.f32.tf32.tf32.f32 " \
        "{%0,%1,%2,%3}, {%4,%5,%6,%7}, {%8,%9}, {%0,%1,%2,%3};" \
        : "+f"((acc)[0]), "+f"((acc)[1]), "+f"((acc)[2]), "+f"((acc)[3]) \
        : "r"(a0), "r"(a1), "r"(a2), "r"(a3), "r"(b0), "r"(b1))

__device__ __forceinline__ void ldsm_x4(uint32_t* r, uint32_t addr) {
    asm volatile("ldmatrix.sync.aligned.m8n8.x4.shared.b16 {%0,%1,%2,%3}, [%4];"
        : "=r"(r[0]), "=r"(r[1]), "=r"(r[2]), "=r"(r[3]) : "r"(addr));
}
__device__ __forceinline__ void ldsm_x2(uint32_t* r, uint32_t addr) {
    asm volatile("ldmatrix.sync.aligned.m8n8.x2.shared.b16 {%0,%1}, [%2];"
        : "=r"(r[0]), "=r"(r[1]) : "r"(addr));
}
#define LDSM_SELS() \
    const int rsel = (lane & 7) + ((lane >> 3) & 1) * 8; \
    const int cA = (lane >> 4) * 4; \
    const int rB = lane & 7; \
    const int cB = ((lane >> 3) & 1) * 4;

// ============================================================
// GEMM body (tf32 warp-MMA, 128x128 tile, RNA rounding at smem store).
// ============================================================
#define GEMM_BODY(A_, W_, EPILOGUE)                                            \
    __shared__ float As[2][128 * 20];                                          \
    __shared__ float Ws[2][128 * 20];                                          \
    const int tid = threadIdx.x;                                               \
    const int wid = tid >> 5, lane = tid & 31;                                 \
    const int wm = wid >> 2, wn = wid & 3;                                     \
    const int bm = blockIdx.y * 128, bn = blockIdx.x * 128;                    \
    LDSM_SELS();                                                               \
    const uint32_t AsU = (uint32_t)__cvta_generic_to_shared(&As[0][0]);        \
    const uint32_t WsU = (uint32_t)__cvta_generic_to_shared(&Ws[0][0]);        \
    int rowA[4], rowB[4];                                                      \
    for (int im = 0; im < 4; im++) rowA[im] = (wm*64 + im*16 + rsel)*20 + cA;  \
    for (int jn = 0; jn < 4; jn++) rowB[jn] = (wn*32 + jn*8 + rB)*20 + cB;     \
    const int p0 = tid, p1 = tid + 256;                                        \
    const int r0 = p0 >> 2, q0 = (p0 & 3) * 4;                                 \
    const int r1 = p1 >> 2, q1 = (p1 & 3) * 4;                                 \
    const float* Arow0 = A_ + (size_t)(bm + r0) * 1024 + q0;                   \
    const float* Arow1 = A_ + (size_t)(bm + r1) * 1024 + q1;                   \
    const float* Wrow0 = W_ + (size_t)(bn + r0) * 1024 + q0;                   \
    const float* Wrow1 = W_ + (size_t)(bn + r1) * 1024 + q1;                   \
    const int s0 = r0 * 20 + q0, s1 = r1 * 20 + q1;                            \
    float acc[4][4][4];                                                        \
    for (int i = 0; i < 4; i++)                                                \
        for (int j = 0; j < 4; j++)                                            \
            for (int q = 0; q < 4; q++) acc[i][j][q] = 0.f;                    \
    {                                                                          \
        float4 va0 = *(const float4*)(Arow0);                                  \
        float4 va1 = *(const float4*)(Arow1);                                  \
        float4 vw0 = *(const float4*)(Wrow0);                                  \
        float4 vw1 = *(const float4*)(Wrow1);                                  \
        uint32_t* a0 = (uint32_t*)&As[0][s0];                                  \
        a0[0]=f2tf32(va0.x); a0[1]=f2tf32(va0.y); a0[2]=f2tf32(va0.z); a0[3]=f2tf32(va0.w); \
        uint32_t* a1 = (uint32_t*)&As[0][s1];                                  \
        a1[0]=f2tf32(va1.x); a1[1]=f2tf32(va1.y); a1[2]=f2tf32(va1.z); a1[3]=f2tf32(va1.w); \
        uint32_t* w0 = (uint32_t*)&Ws[0][s0];                                  \
        w0[0]=f2tf32(vw0.x); w0[1]=f2tf32(vw0.y); w0[2]=f2tf32(vw0.z); w0[3]=f2tf32(vw0.w); \
        uint32_t* w1 = (uint32_t*)&Ws[0][s1];                                  \
        w1[0]=f2tf32(vw1.x); w1[1]=f2tf32(vw1.y); w1[2]=f2tf32(vw1.z); w1[3]=f2tf32(vw1.w); \
    }                                                                          \
    __syncthreads();                                                           \
    for (int c = 0; c < 64; c++) {                                             \
        const int buf = c & 1;                                                 \
        const uint32_t aBuf = AsU + (uint32_t)buf * (128 * 20 * 4);            \
        const uint32_t wBuf = WsU + (uint32_t)buf * (128 * 20 * 4);            \
        float4 ra0, ra1, rw0, rw1;                                             \
        if (c < 63) {                                                          \
            const int k0 = (c + 1) * 16;                                       \
            ra0 = *(const float4*)(Arow0 + k0);                                \
            ra1 = *(const float4*)(Arow1 + k0);                                \
            rw0 = *(const float4*)(Wrow0 + k0);                                \
            rw1 = *(const float4*)(Wrow1 + k0);                                \
        }                                                                      \
        for (int ks = 0; ks < 2; ks++) {                                       \
            const int kk = ks * 8;                                             \
            uint32_t af[4][4], bf[4][2];                                       \
            for (int im = 0; im < 4; im++)                                     \
                ldsm_x4(af[im], aBuf + (uint32_t)(rowA[im] + kk) * 4);         \
            for (int jn = 0; jn < 4; jn++)                                     \
                ldsm_x2(bf[jn], wBuf + (uint32_t)(rowB[jn] + kk) * 4);         \
            for (int im = 0; im < 4; im++)                                     \
                for (int jn = 0; jn < 4; jn++)                                 \
                    MMA_TF32(acc[im][jn], af[im][0], af[im][1], af[im][2], af[im][3], \
                             bf[jn][0], bf[jn][1]);                            \
        }                                                                      \
        if (c < 63) {                                                          \
            const int nxt = buf ^ 1;                                           \
            uint32_t* a0 = (uint32_t*)&As[nxt][s0];                            \
            a0[0]=f2tf32(ra0.x); a0[1]=f2tf32(ra0.y); a0[2]=f2tf32(ra0.z); a0[3]=f2tf32(ra0.w); \
            uint32_t* a1 = (uint32_t*)&As[nxt][s1];                            \
            a1[0]=f2tf32(ra1.x); a1[1]=f2tf32(ra1.y); a1[2]=f2tf32(ra1.z); a1[3]=f2tf32(ra1.w); \
            uint32_t* w0 = (uint32_t*)&Ws[nxt][s0];                            \
            w0[0]=f2tf32(rw0.x); w0[1]=f2tf32(rw0.y); w0[2]=f2tf32(rw0.z); w0[3]=f2tf32(rw0.w); \
            uint32_t* w1 = (uint32_t*)&Ws[nxt][s1];                            \
            w1[0]=f2tf32(rw1.x); w1[1]=f2tf32(rw1.y); w1[2]=f2tf32(rw1.z); w1[3]=f2tf32(rw1.w); \
        }                                                                      \
        __syncthreads();                                                       \
    }                                                                          \
    const int g = lane >> 2, t = lane & 3;                                     \
    EPILOGUE

// QKV + maskbits fused launch: z in {0,1,2} -> GEMM (pre-rounded tf32 out),
// z==3 -> mask float -> bit conversion (overlaps bandwidth with GEMM latency).
__global__ void __launch_bounds__(256, 2)
qkv_gemm_kernel(const float* __restrict__ enc,
                const float* __restrict__ WQ, const float* __restrict__ WK,
                const float* __restrict__ WV, const float* __restrict__ mask,
                float* __restrict__ Qo, float* __restrict__ Ko, float* __restrict__ Vo,
                unsigned int* __restrict__ mb) {
    const int z = blockIdx.z;
    if (z == 3) {
        // 256 blocks x 256 threads x 128 elems = 8.4M elems (B*S*S)
        const int p = blockIdx.y * 8 + blockIdx.x;        // 0..255
        size_t base = (size_t)p * 32768 + threadIdx.x;
#pragma unroll 4
        for (int j = 0; j < 128; j++) {
            size_t i = base + (size_t)j * 256;
            float m = mask[i];
            unsigned int bal = __ballot_sync(0xffffffffu, m != 0.f);
            if ((threadIdx.x & 31) == 0) mb[i >> 5] = bal;
        }
        return;
    }
    const float* Wsel = (z == 0) ? WQ : (z == 1) ? WK : WV;
    float* Csel = (z == 0) ? Qo : (z == 1) ? Ko : Vo;
    GEMM_BODY(enc, Wsel,
        {
            for (int im = 0; im < 4; im++) {
                const int rowAo = bm + wm * 64 + im * 16 + g;
                const int rowBo = rowAo + 8;
                for (int jn = 0; jn < 4; jn++) {
                    const int col = bn + wn * 32 + jn * 8 + 2 * t;
                    float2 vA = make_float2(__uint_as_float(f2tf32(acc[im][jn][0])),
                                            __uint_as_float(f2tf32(acc[im][jn][1])));
                    float2 vB = make_float2(__uint_as_float(f2tf32(acc[im][jn][2])),
                                            __uint_as_float(f2tf32(acc[im][jn][3])));
                    *(float2*)(Csel + (size_t)rowAo * 1024 + col) = vA;
                    *(float2*)(Csel + (size_t)rowBo * 1024 + col) = vB;
                }
            }
        })
}

// WO: residual-add epilogue, full fp32 output.
__global__ void __launch_bounds__(256, 2)
gemm_res_kernel(const float* __restrict__ A, const float* __restrict__ W,
                float* __restrict__ C, const float* __restrict__ res) {
    GEMM_BODY(A, W,
        {
            for (int im = 0; im < 4; im++) {
                const int rowAo = bm + wm * 64 + im * 16 + g;
                const int rowBo = rowAo + 8;
                for (int jn = 0; jn < 4; jn++) {
                    const int col = bn + wn * 32 + jn * 8 + 2 * t;
                    float2 rA = *(const float2*)(res + (size_t)rowAo * 1024 + col);
                    float2 rB2 = *(const float2*)(res + (size_t)rowBo * 1024 + col);
                    *(float2*)(C + (size_t)rowAo * 1024 + col) =
                        make_float2(acc[im][jn][0] + rA.x, acc[im][jn][1] + rA.y);
                    *(float2*)(C + (size_t)rowBo * 1024 + col) =
                        make_float2(acc[im][jn][2] + rB2.x, acc[im][jn][3] + rB2.y);
                }
            }
        })
}

// ============================================================
// Fused attention: phase 1 computes row sums (inv) in-block, phase 2
// recomputes S, writes attn once (coalesced), accumulates O via MMA.
// Q/K/V pre-rounded tf32 -> raw float4 loads. V row-major; AV B-frags
// loaded with direct LDS (no transpose STS, no V ldsm).
// smem floats: Qs[8704]@0, Ks[4352]@8704, Vs[4352]@13056, stage[8704]@17408
// (phase-1 sumbuf overlays stage), maskS(256u)@26112, invS[128]@26368.
// ============================================================
__global__ void __launch_bounds__(256, 2)
fused_attn_kernel(const float* __restrict__ Qb, const float* __restrict__ Kb,
                  const float* __restrict__ Vb, const unsigned int* __restrict__ mb,
                  float* __restrict__ attn, float* __restrict__ Ob) {
    extern __shared__ float sm[];
    float* Qs = sm;
    float* Ks = sm + 8704;
    float* Vs = sm + 13056;
    float* stage = sm + 17408;
    float* sumbuf = sm + 17408;                         // overlays stage (phase 1)
    unsigned int* maskS = (unsigned int*)(sm + 26112);
    float* invS = sm + 26368;

    const int tid = threadIdx.x;
    const int wid = tid >> 5, lane = tid & 31;
    const int wm = wid >> 2, wn = wid & 3;
    const int bh = blockIdx.y, b = bh >> 4, h = bh & 15;
    const int q0 = blockIdx.x * 128;
    LDSM_SELS();
    const int g = lane >> 2, t = lane & 3;

    const uint32_t QsU = (uint32_t)__cvta_generic_to_shared(Qs);
    const uint32_t KsU = (uint32_t)__cvta_generic_to_shared(Ks);
    const uint32_t StU = (uint32_t)__cvta_generic_to_shared(stage);

    int rowQ[4], rowK[2];
#pragma unroll
    for (int im = 0; im < 4; im++) rowQ[im] = (wm * 64 + im * 16 + rsel) * 68 + cA;
#pragma unroll
    for (int jn = 0; jn < 2; jn++) rowK[jn] = (wn * 16 + jn * 8 + rB) * 68 + cB;

    const float* Qbase = Qb + ((size_t)(b * SS + q0)) * HH + h * HDD;
    const float* Kbase = Kb + ((size_t)b * SS) * HH + h * HDD;
    const float* Vbase = Vb + ((size_t)b * SS) * HH + h * HDD;
    const int lr = tid >> 4, lc4 = (tid & 15) * 4;
    const int mr = tid >> 1, mw = tid & 1;

    // Q loaded once for both phases
#pragma unroll
    for (int j = 0; j < 8; j++) {
        int idx = tid + j * 256;
        int r = idx >> 4, c4 = (idx & 15) * 4;
        *(float4*)&Qs[r * 68 + c4] = *(const float4*)(Qbase + (size_t)r * HH + c4);
    }
    // phase-1 tile 0: K + mask
#pragma unroll
    for (int j = 0; j < 4; j++) {
        int r = lr + j * 16;
        *(float4*)&Ks[r * 68 + lc4] = *(const float4*)(Kbase + (size_t)r * HH + lc4);
    }
    maskS[tid] = mb[(size_t)(b * SS + q0 + mr) * 64 + mw];
    __syncthreads();

    // ================= PHASE 1: row sums =================
    float rsA[4], rsB[4];
#pragma unroll
    for (int im = 0; im < 4; im++) { rsA[im] = 0.f; rsB[im] = 0.f; }

    for (int kt = 0; kt < 32; kt++) {
        const bool pf = (kt < 31);
        float4 rk[4];
        unsigned int rm = 0;
        if (pf) {
            const int n1 = (kt + 1) * 64;
#pragma unroll
            for (int j = 0; j < 4; j++)
                rk[j] = *(const float4*)(Kbase + (size_t)(n1 + lr + j * 16) * HH + lc4);
            rm = mb[(size_t)(b * SS + q0 + mr) * 64 + (n1 >> 5) + mw];
        }

        float acc[4][2][4];
#pragma unroll
        for (int i = 0; i < 4; i++)
#pragma unroll
            for (int j = 0; j < 2; j++)
#pragma unroll
                for (int q = 0; q < 4; q++) acc[i][j][q] = 0.f;
#pragma unroll
        for (int ks = 0; ks < 8; ks++) {
            const int kk = ks * 8;
            uint32_t af[4][4], bf[2][2];
#pragma unroll
            for (int im = 0; im < 4; im++)
                ldsm_x4(af[im], QsU + (uint32_t)(rowQ[im] + kk) * 4);
#pragma unroll
            for (int jn = 0; jn < 2; jn++)
                ldsm_x2(bf[jn], KsU + (uint32_t)(rowK[jn] + kk) * 4);
#pragma unroll
            for (int im = 0; im < 4; im++)
#pragma unroll
                for (int jn = 0; jn < 2; jn++)
                    MMA_TF32(acc[im][jn], af[im][0], af[im][1], af[im][2], af[im][3],
                             bf[jn][0], bf[jn][1]);
        }

#pragma unroll
        for (int im = 0; im < 4; im++) {
            const int rAl = wm * 64 + im * 16 + g;
            const int rBl = rAl + 8;
#pragma unroll
            for (int jn = 0; jn < 2; jn++) {
                const int bp = wn * 16 + jn * 8 + 2 * t;
                const unsigned int wA = maskS[rAl * 2 + (bp >> 5)];
                const unsigned int wB = maskS[rBl * 2 + (bp >> 5)];
                const int bi = bp & 31;
                if ((wA >> bi) & 1u)       rsA[im] += __expf(acc[im][jn][0] * 0.125f);
                if ((wA >> (bi + 1)) & 1u) rsA[im] += __expf(acc[im][jn][1] * 0.125f);
                if ((wB >> bi) & 1u)       rsB[im] += __expf(acc[im][jn][2] * 0.125f);
                if ((wB >> (bi + 1)) & 1u) rsB[im] += __expf(acc[im][jn][3] * 0.125f);
            }
        }
        __syncthreads();
        if (pf) {
#pragma unroll
            for (int j = 0; j < 4; j++)
                *(float4*)&Ks[(lr + j * 16) * 68 + lc4] = rk[j];
            maskS[tid] = rm;
        }
        __syncthreads();
    }

#pragma unroll
    for (int im = 0; im < 4; im++) {
        float a = rsA[im], bb = rsB[im];
        a += __shfl_xor_sync(0xffffffffu, a, 1);
        a += __shfl_xor_sync(0xffffffffu, a, 2);
        bb += __shfl_xor_sync(0xffffffffu, bb, 1);
        bb += __shfl_xor_sync(0xffffffffu, bb, 2);
        if (t == 0) {
            sumbuf[(wm * 64 + im * 16 + g) * 4 + wn] = a;
            sumbuf[(wm * 64 + im * 16 + g + 8) * 4 + wn] = bb;
        }
    }
    __syncthreads();
    if (tid < 128) {
        float s = sumbuf[tid * 4] + sumbuf[tid * 4 + 1] +
                  sumbuf[tid * 4 + 2] + sumbuf[tid * 4 + 3];
        invS[tid] = (s > 0.f) ? 1.f / s : 0.f;
    }
    // phase-2 tile 0: K, V (row-major), mask
    __syncthreads();
#pragma unroll
    for (int j = 0; j < 4; j++) {
        int r = lr + j * 16;
        *(float4*)&Ks[r * 68 + lc4] = *(const float4*)(Kbase + (size_t)r * HH + lc4);
        *(float4*)&Vs[r * 68 + lc4] = *(const float4*)(Vbase + (size_t)r * HH + lc4);
    }
    maskS[tid] = mb[(size_t)(b * SS + q0 + mr) * 64 + mw];
    __syncthreads();

    // ================= PHASE 2: attn write + AV =================
    float accO[4][2][4];
#pragma unroll
    for (int i = 0; i < 4; i++)
#pragma unroll
        for (int j = 0; j < 2; j++)
#pragma unroll
            for (int q = 0; q < 4; q++) accO[i][j][q] = 0.f;

    for (int kt = 0; kt < 32; kt++) {
        const int k0 = kt * 64;
        const bool pf = (kt < 31);
        float4 rk[4];
        unsigned int rm = 0;
        if (pf) {
#pragma unroll
            for (int j = 0; j < 4; j++)
                rk[j] = *(const float4*)(Kbase + (size_t)(k0 + 64 + lr + j * 16) * HH + lc4);
            rm = mb[(size_t)(b * SS + q0 + mr) * 64 + ((k0 + 64) >> 5) + mw];
        }

        // --- S = Q K^T ---
        float acc[4][2][4];
#pragma unroll
        for (int i = 0; i < 4; i++)
#pragma unroll
            for (int j = 0; j < 2; j++)
#pragma unroll
                for (int q = 0; q < 4; q++) acc[i][j][q] = 0.f;
#pragma unroll
        for (int ks = 0; ks < 8; ks++) {
            const int kk = ks * 8;
            uint32_t af[4][4], bf[2][2];
#pragma unroll
            for (int im = 0; im < 4; im++)
                ldsm_x4(af[im], QsU + (uint32_t)(rowQ[im] + kk) * 4);
#pragma unroll
            for (int jn = 0; jn < 2; jn++)
                ldsm_x2(bf[jn], KsU + (uint32_t)(rowK[jn] + kk) * 4);
#pragma unroll
            for (int im = 0; im < 4; im++)
#pragma unroll
                for (int jn = 0; jn < 2; jn++)
                    MMA_TF32(acc[im][jn], af[im][0], af[im][1], af[im][2], af[im][3],
                             bf[jn][0], bf[jn][1]);
        }

        // --- attn = mask ? exp(S/8)*inv : 0 -> stage (fp32) ---
#pragma unroll
        for (int im = 0; im < 4; im++) {
            const int rAl = wm * 64 + im * 16 + g;
            const int rBl = rAl + 8;
            const float ivA = invS[rAl], ivB = invS[rBl];
#pragma unroll
            for (int jn = 0; jn < 2; jn++) {
                const int bp = wn * 16 + jn * 8 + 2 * t;
                const unsigned int wA = maskS[rAl * 2 + (bp >> 5)];
                const unsigned int wB = maskS[rBl * 2 + (bp >> 5)];
                const int bi = bp & 31;
                float e0 = ((wA >> bi) & 1u)       ? __expf(acc[im][jn][0] * 0.125f) * ivA : 0.f;
                float e1 = ((wA >> (bi + 1)) & 1u) ? __expf(acc[im][jn][1] * 0.125f) * ivA : 0.f;
                float e2 = ((wB >> bi) & 1u)       ? __expf(acc[im][jn][2] * 0.125f) * ivB : 0.f;
                float e3 = ((wB >> (bi + 1)) & 1u) ? __expf(acc[im][jn][3] * 0.125f) * ivB : 0.f;
                *(float2*)&stage[rAl * 68 + bp] = make_float2(e0, e1);
                *(float2*)&stage[rBl * 68 + bp] = make_float2(e2, e3);
            }
        }
        // prefetch V(kt+1) (in flight across AV phase)
        float4 rv[4];
        if (pf) {
#pragma unroll
            for (int j = 0; j < 4; j++)
                rv[j] = *(const float4*)(Vbase + (size_t)(k0 + 64 + lr + j * 16) * HH + lc4);
        }
        __syncthreads();    // stage visible; QK done with Ks

        // --- AV MMA: O += P(stage, ldsm) * V(Vs row-major, direct LDS b-frags) ---
#pragma unroll
        for (int ks = 0; ks < 8; ks++) {
            const int kk = ks * 8;
            uint32_t af[4][4];
            float bf0[2], bf1[2];
#pragma unroll
            for (int im = 0; im < 4; im++)
                ldsm_x4(af[im], StU + (uint32_t)(rowQ[im] + kk) * 4);
#pragma unroll
            for (int jd = 0; jd < 2; jd++) {
                const int nc = wn * 16 + jd * 8 + g;
                bf0[jd] = Vs[(kk + t) * 68 + nc];
                bf1[jd] = Vs[(kk + t + 4) * 68 + nc];
            }
#pragma unroll
            for (int im = 0; im < 4; im++)
#pragma unroll
                for (int jd = 0; jd < 2; jd++)
                    MMA_TF32(accO[im][jd], af[im][0], af[im][1], af[im][2], af[im][3],
                             __float_as_uint(bf0[jd]), __float_as_uint(bf1[jd]));
        }

        // --- coalesced attn write from stage ---
        float* abase = attn + ((size_t)(bh * SS + q0)) * SS + k0;
#pragma unroll
        for (int j = 0; j < 8; j++) {
            int idx = tid + j * 256;
            int r = idx >> 4, c4 = (idx & 15) * 4;
            float4 v = *(float4*)&stage[r * 68 + c4];
            *(float4*)(abase + (size_t)r * SS + c4) = v;
        }
        __syncthreads();    // Ks/Vs/maskS free
        if (pf) {
#pragma unroll
            for (int j = 0; j < 4; j++) {
                int r = lr + j * 16;
                *(float4*)&Ks[r * 68 + lc4] = rk[j];
                *(float4*)&Vs[r * 68 + lc4] = rv[j];
            }
            maskS[tid] = rm;
        }
        __syncthreads();
    }

    // --- O epilogue ---
#pragma unroll
    for (int im = 0; im < 4; im++) {
        const int rowAo = q0 + wm * 64 + im * 16 + g;
        const int rowBo = rowAo + 8;
#pragma unroll
        for (int jd = 0; jd < 2; jd++) {
            const int col = h * HDD + wn * 16 + jd * 8 + 2 * t;
            *(float2*)(Ob + (size_t)(b * SS + rowAo) * HH + col) =
                make_float2(accO[im][jd][0], accO[im][jd][1]);
            *(float2*)(Ob + (size_t)(b * SS + rowBo) * HH + col) =
                make_float2(accO[im][jd][2], accO[im][jd][3]);
        }
    }
}

// ============================================================
// LayerNorm
// ============================================================
__global__ void ln_kernel(const float* __restrict__ X,
                          const float* __restrict__ w,
                          const float* __restrict__ bias,
                          float* __restrict__ Y) {
    __shared__ float red[8];
    __shared__ float bc;
    const int row = blockIdx.x;
    const float* x = X + (size_t)row * HH;
    const int tid = threadIdx.x, lane = tid & 31, warp = tid >> 5;

    float s = 0.f;
    for (int c = tid; c < HH; c += 256) s += x[c];
#pragma unroll
    for (int o = 16; o; o >>= 1) s += __shfl_xor_sync(0xffffffffu, s, o);
    if (lane == 0) red[warp] = s;
    __syncthreads();
    if (tid == 0) {
        float tt = 0.f;
        for (int i = 0; i < 8; i++) tt += red[i];
        bc = tt / HH;
    }
    __syncthreads();
    float mu = bc;

    float v = 0.f;
    for (int c = tid; c < HH; c += 256) { float d = x[c] - mu; v += d * d; }
#pragma unroll
    for (int o = 16; o; o >>= 1) v += __shfl_xor_sync(0xffffffffu, v, o);
    if (lane == 0) red[warp] = v;
    __syncthreads();
    if (tid == 0) {
        float tt = 0.f;
        for (int i = 0; i < 8; i++) tt += red[i];
        bc = rsqrtf(tt / HH + 1e-6f);
    }
    __syncthreads();
    float inv = bc;

    for (int c = tid; c < HH; c += 256)
        Y[(size_t)row * HH + c] = (x[c] - mu) * inv * w[c] + bias[c];
}

// ============================================================
extern "C" void kernel_launch(void* const* d_in, const int* in_sizes, int n_in,
                              void* d_out, int out_size) {
    const float* enc  = (const float*)d_in[0];
    const float* mask = (const float*)d_in[1];
    const float* WQ   = (const float*)d_in[2];
    const float* WK   = (const float*)d_in[3];
    const float* WV   = (const float*)d_in[4];
    const float* WO   = (const float*)d_in[5];
    const float* lnw  = (const float*)d_in[6];
    const float* lnb  = (const float*)d_in[7];

    float* y    = (float*)d_out;              // (B,S,H)
    float* attn = y + (size_t)Y_SIZE;         // (B,NH,S,S)

    float *Qp, *Kp, *Vp, *Op, *Xp;
    unsigned int* Mp;
    cudaGetSymbolAddress((void**)&Qp, g_Q);
    cudaGetSymbolAddress((void**)&Kp, g_K);
    cudaGetSymbolAddress((void**)&Vp, g_V);
    cudaGetSymbolAddress((void**)&Op, g_AO);
    cudaGetSymbolAddress((void**)&Xp, g_X);
    cudaGetSymbolAddress((void**)&Mp, g_MB);

    qkv_gemm_kernel<<<dim3(HH / 128, MM / 128, 4), 256>>>(enc, WQ, WK, WV, mask,
                                                          Qp, Kp, Vp, Mp);

    const int fa_smem = 26496 * (int)sizeof(float);    // 105984
    cudaFuncSetAttribute(fused_attn_kernel,
                         cudaFuncAttributeMaxDynamicSharedMemorySize, fa_smem);
    fused_attn_kernel<<<dim3(SS / 128, BB * NHH), 256, fa_smem>>>(Qp, Kp, Vp, Mp, attn, Op);

    gemm_res_kernel<<<dim3(HH / 128, MM / 128), 256>>>(Op, WO, Xp, enc);

    ln_kernel<<<MM, 256>>>(Xp, lnw, lnb, y);
}